// round 15
// baseline (speedup 1.0000x reference)
#include <cuda_runtime.h>
#include <cuda_fp16.h>
#include <math.h>
#include <stdint.h>

#define Bz 8
#define Sq 1024
#define Dm 1024
#define Hh 16
#define DH 64
#define Ii 4096
#define ROWS (Bz * Sq)

// ---------------- scratch (static device memory; no allocations) ----------------
__device__ __half g_seqh[ROWS * Dm], g_seql[ROWS * Dm];
__device__ __half g_Bqkh[2048 * Dm], g_Bqkl[2048 * Dm];
__device__ __half g_Bvh[1024 * Dm];
__device__ __half g_Woh[Dm * Dm];
__device__ __half g_Wih[Ii * Dm];
__device__ __half g_Wouth[Dm * Ii];
__device__ __half g_qh[ROWS * Dm], g_ql[ROWS * Dm];
__device__ __half g_kh[ROWS * Dm], g_kl[ROWS * Dm];
__device__ __half g_vh[ROWS * Dm];
__device__ __half g_ctxh[ROWS * Dm];
__device__ __half g_attnh[ROWS * Dm];
__device__ float g_x[ROWS * Dm];
__device__ __half g_xh[ROWS * Dm];
__device__ __half g_hh[ROWS * Ii];
__device__ __half g_yh[ROWS * Dm];

// ---------------- helpers ----------------
__device__ __forceinline__ uint32_t smem_u32(const void* p) {
    uint32_t r;
    asm("{ .reg .u64 t; cvta.to.shared.u64 t, %1; cvt.u32.u64 %0, t; }" : "=r"(r) : "l"(p));
    return r;
}
#define CP_ASYNC16(dst, src) \
    asm volatile("cp.async.cg.shared.global [%0], [%1], 16;" :: "r"(dst), "l"(src) : "memory")
#define CP_COMMIT() asm volatile("cp.async.commit_group;" ::: "memory")
#define CP_WAIT1()  asm volatile("cp.async.wait_group 1;" ::: "memory")
#define CP_WAIT0()  asm volatile("cp.async.wait_group 0;" ::: "memory")

__device__ __forceinline__ void mma16816(float* d, const uint32_t* a, const uint32_t* b) {
    asm volatile(
        "mma.sync.aligned.m16n8k16.row.col.f32.f16.f16.f32 "
        "{%0,%1,%2,%3}, {%4,%5,%6,%7}, {%8,%9}, {%0,%1,%2,%3};"
        : "+f"(d[0]), "+f"(d[1]), "+f"(d[2]), "+f"(d[3])
        : "r"(a[0]), "r"(a[1]), "r"(a[2]), "r"(a[3]), "r"(b[0]), "r"(b[1]));
}
__device__ __forceinline__ void ldsm4(uint32_t* r, uint32_t a) {
    asm volatile("ldmatrix.sync.aligned.m8n8.x4.shared.b16 {%0,%1,%2,%3}, [%4];"
                 : "=r"(r[0]), "=r"(r[1]), "=r"(r[2]), "=r"(r[3]) : "r"(a));
}
__device__ __forceinline__ void ldsm4t(uint32_t* r, uint32_t a) {
    asm volatile("ldmatrix.sync.aligned.m8n8.x4.trans.shared.b16 {%0,%1,%2,%3}, [%4];"
                 : "=r"(r[0]), "=r"(r[1]), "=r"(r[2]), "=r"(r[3]) : "r"(a));
}
__device__ __forceinline__ uint32_t packh2(float a, float b) {
    __half2 h = __floats2half2_rn(a, b);
    return *(uint32_t*)&h;
}
// Branch-free erf, Abramowitz-Stegun 7.1.26 (|err| <= 1.5e-7)
__device__ __forceinline__ float erf_fast(float x) {
    float ax = fabsf(x);
    float t = __fdividef(1.0f, fmaf(0.3275911f, ax, 1.0f));
    float p = t * fmaf(t, fmaf(t, fmaf(t, fmaf(t, 1.061405429f, -1.453152027f),
                                       1.421413741f), -0.284496736f), 0.254829592f);
    float r = 1.0f - p * __expf(-ax * ax);
    return copysignf(r, x);
}
__device__ __forceinline__ float gelu_fast(float v) {
    return 0.5f * v * (1.0f + erf_fast(v * 0.70710678118654752f));
}

// ---------------- weight pack: per-head column window, transpose + fp16 (hi[/lo]) ----
__global__ void packW_kernel(const float* __restrict__ w, __half* __restrict__ oh,
                             __half* __restrict__ ol, int K, int N, int ncol0, int nout) {
    __shared__ float t[32][33];
    const int z = blockIdx.z;
    const float* in = w + (size_t)z * K * N;
    __half* poh = oh + (size_t)z * nout * K;
    __half* pol = ol ? ol + (size_t)z * nout * K : nullptr;
    const int n0 = blockIdx.x * 32, k0 = blockIdx.y * 32;
    const int tx = threadIdx.x, ty = threadIdx.y;
#pragma unroll
    for (int i = 0; i < 32; i += 8)
        t[ty + i][tx] = in[(size_t)(k0 + ty + i) * N + ncol0 + n0 + tx];
    __syncthreads();
#pragma unroll
    for (int i = 0; i < 32; i += 8) {
        float v = t[tx][ty + i];
        __half hi = __float2half_rn(v);
        size_t o = (size_t)(n0 + ty + i) * K + k0 + tx;
        poh[o] = hi;
        if (pol) pol[o] = __float2half_rn(v - __half2float(hi));
    }
}

// ---------------- fp32 -> fp16 hi/lo ----------------
__global__ void split_kernel(const float* __restrict__ in, __half* __restrict__ oh,
                             __half* __restrict__ ol, int n) {
    int i = (blockIdx.x * 256 + threadIdx.x) * 4;
    if (i < n) {
        float4 v = *(const float4*)(in + i);
        __half h0 = __float2half_rn(v.x), h1 = __float2half_rn(v.y);
        __half h2 = __float2half_rn(v.z), h3 = __float2half_rn(v.w);
        __half2* ph = (__half2*)(oh + i);
        ph[0] = __halves2half2(h0, h1);
        ph[1] = __halves2half2(h2, h3);
        __half2* pl = (__half2*)(ol + i);
        pl[0] = __halves2half2(__float2half_rn(v.x - __half2float(h0)),
                               __float2half_rn(v.y - __half2float(h1)));
        pl[1] = __halves2half2(__float2half_rn(v.z - __half2float(h2)),
                               __float2half_rn(v.w - __half2float(h3)));
    }
}

#define SROW 72
#define TILE_H (128 * SROW)
#define TILE_B (TILE_H * 2)            // 18432 bytes (128 rows)
#define HTILE_B (64 * SROW * 2)        // 9216 bytes (64 rows)

// ---------------- 3-term QK GEMM: 128x64 block tile, occ 2 ----------------
// 8 warps: wm=(w>>1)*32, wn=(w&1)*32; warp tile 32x32.
// EPI: QK scatter (N=2048): c -> h=c>>7, e=c&127; e<64: q*8 hi/lo, else k hi/lo
#define QKSTAGE_B (2 * TILE_B + 2 * HTILE_B)   // 55296
#define QK_SMEM (2 * QKSTAGE_B)                // 110592

__global__ __launch_bounds__(256, 2)
void mma_gemm_qk(const __half* __restrict__ Ah, const __half* __restrict__ Al,
                 const __half* __restrict__ Bh, const __half* __restrict__ Bl,
                 const float* __restrict__ bias,
                 __half* __restrict__ qh, __half* __restrict__ ql,
                 __half* __restrict__ kh, __half* __restrict__ kl,
                 int K, int N) {
    extern __shared__ char smem[];
    const uint32_t sb = smem_u32(smem);
    const int tid = threadIdx.x;
    const int w = tid >> 5, lane = tid & 31;
    const int g = lane >> 2, tig = lane & 3;
    const int quad = lane >> 3, lr = lane & 7;
    const int bm = blockIdx.y, bn = blockIdx.x;
    const int wm = (w >> 1) * 32;      // 0,32,64,96
    const int wn = (w & 1) * 32;       // 0,32

    const uint32_t aoff = (((quad & 1) * 8 + lr) * SROW + (quad >> 1) * 8) * 2;
    const uint32_t boff = (((quad >> 1) * 8 + lr) * SROW + (quad & 1) * 8) * 2;

    const __half* gAh = Ah + (size_t)bm * 128 * K;
    const __half* gAl = Al + (size_t)bm * 128 * K;
    const __half* gBh = Bh + (size_t)bn * 64 * K;
    const __half* gBl = Bl + (size_t)bn * 64 * K;

    float acc[2][4][4];
#pragma unroll
    for (int mi = 0; mi < 2; mi++)
#pragma unroll
        for (int ni = 0; ni < 4; ni++)
#pragma unroll
            for (int e = 0; e < 4; e++) acc[mi][ni][e] = 0.f;

    const int NT = K / 64;

    auto issue_stage = [&](int kt) {
        const uint32_t dstS = sb + (kt & 1) * QKSTAGE_B;
        // A hi/lo: 2 x 1024 chunks
#pragma unroll
        for (int i = 0; i < 4; i++) {
            const int c = tid + i * 256;
            const int row = c >> 3, col = c & 7;
            CP_ASYNC16(dstS + row * (SROW * 2) + col * 16,
                       gAh + (size_t)(kt * 64) + (size_t)row * K + col * 8);
            CP_ASYNC16(dstS + TILE_B + row * (SROW * 2) + col * 16,
                       gAl + (size_t)(kt * 64) + (size_t)row * K + col * 8);
        }
        // B hi/lo: 2 x 512 chunks
#pragma unroll
        for (int i = 0; i < 2; i++) {
            const int c = tid + i * 256;
            const int row = c >> 3, col = c & 7;
            CP_ASYNC16(dstS + 2 * TILE_B + row * (SROW * 2) + col * 16,
                       gBh + (size_t)(kt * 64) + (size_t)row * K + col * 8);
            CP_ASYNC16(dstS + 2 * TILE_B + HTILE_B + row * (SROW * 2) + col * 16,
                       gBl + (size_t)(kt * 64) + (size_t)row * K + col * 8);
        }
        CP_COMMIT();
    };

    issue_stage(0);

    for (int kt = 0; kt < NT; kt++) {
        if (kt + 1 < NT) { issue_stage(kt + 1); CP_WAIT1(); } else { CP_WAIT0(); }
        __syncthreads();

        const uint32_t sA  = sb + (kt & 1) * QKSTAGE_B;
        const uint32_t sAl = sA + TILE_B;
        const uint32_t sBh = sA + 2 * TILE_B;
        const uint32_t sBl = sBh + HTILE_B;

#pragma unroll
        for (int ks = 0; ks < 4; ks++) {
            const uint32_t k0b = (uint32_t)(ks * 16) * 2;
            uint32_t ah[2][4], al[2][4], bh[4][2], bl[4][2];
#pragma unroll
            for (int mi = 0; mi < 2; mi++) {
                const uint32_t rbase = (uint32_t)((wm + mi * 16) * SROW) * 2 + k0b;
                ldsm4(ah[mi], sA + rbase + aoff);
                ldsm4(al[mi], sAl + rbase + aoff);
            }
#pragma unroll
            for (int np = 0; np < 2; np++) {
                const uint32_t rbase = (uint32_t)((wn + np * 16) * SROW) * 2 + k0b;
                uint32_t rr[4];
                ldsm4(rr, sBh + rbase + boff);
                bh[2 * np][0] = rr[0]; bh[2 * np][1] = rr[1];
                bh[2 * np + 1][0] = rr[2]; bh[2 * np + 1][1] = rr[3];
                ldsm4(rr, sBl + rbase + boff);
                bl[2 * np][0] = rr[0]; bl[2 * np][1] = rr[1];
                bl[2 * np + 1][0] = rr[2]; bl[2 * np + 1][1] = rr[3];
            }
#pragma unroll
            for (int mi = 0; mi < 2; mi++)
#pragma unroll
                for (int ni = 0; ni < 4; ni++) {
                    mma16816(acc[mi][ni], ah[mi], bh[ni]);
                    mma16816(acc[mi][ni], ah[mi], bl[ni]);
                    mma16816(acc[mi][ni], al[mi], bh[ni]);
                }
        }
        __syncthreads();
    }

#pragma unroll
    for (int mi = 0; mi < 2; mi++) {
#pragma unroll
        for (int half_ = 0; half_ < 2; half_++) {
            const int row = bm * 128 + wm + mi * 16 + g + half_ * 8;
#pragma unroll
            for (int ni = 0; ni < 4; ni++) {
                const int c = bn * 64 + wn + ni * 8 + tig * 2;
                const int h = c >> 7;
                const int e = c & 127;
                float v0 = acc[mi][ni][half_ * 2 + 0] + bias[h * 192 + e];
                float v1 = acc[mi][ni][half_ * 2 + 1] + bias[h * 192 + e + 1];
                const int b_ = row >> 10, s_ = row & 1023;
                const size_t base = ((size_t)(b_ * Hh + h) * Sq + s_) * DH;
                if (e < DH) {
                    float s0 = v0 * 8.0f, s1 = v1 * 8.0f;   // sqrt(DH)=8
                    __half h0 = __float2half_rn(s0), h1 = __float2half_rn(s1);
                    *(__half2*)&qh[base + e] = __halves2half2(h0, h1);
                    *(__half2*)&ql[base + e] =
                        __halves2half2(__float2half_rn(s0 - __half2float(h0)),
                                       __float2half_rn(s1 - __half2float(h1)));
                } else {
                    __half h0 = __float2half_rn(v0), h1 = __float2half_rn(v1);
                    *(__half2*)&kh[base + e - DH] = __halves2half2(h0, h1);
                    *(__half2*)&kl[base + e - DH] =
                        __halves2half2(__float2half_rn(v0 - __half2float(h0)),
                                       __float2half_rn(v1 - __half2float(h1)));
                }
            }
        }
    }
}

// ---------------- 1-term GEMM (128x128 tile, occ 2 — proven R13 config) ----------------
// EPI 2: Oh = fp16(gelu(v + bias[c]))
// EPI 4: V scatter (N=1024): c -> h=c>>6, d=c&63 -> vh fp16
// EPI 5: Oh = fp16(v + bias[c])
#define W1STAGE_B (2 * TILE_B)
#define W1_SMEM (2 * W1STAGE_B)        // 73728

template <int EPI>
__global__ __launch_bounds__(256, 2)
void mma_gemm_w(const __half* __restrict__ Ah, const __half* __restrict__ Bh,
                const float* __restrict__ bias,
                __half* __restrict__ vh, __half* __restrict__ Oh,
                int K, int N) {
    extern __shared__ char smem[];
    const uint32_t sb = smem_u32(smem);
    const int tid = threadIdx.x;
    const int w = tid >> 5, lane = tid & 31;
    const int g = lane >> 2, tig = lane & 3;
    const int quad = lane >> 3, lr = lane & 7;
    const int bm = blockIdx.y, bn = blockIdx.x;
    const int wm = (w >> 2) * 64;
    const int wn = (w & 3) * 32;

    const uint32_t aoff = (((quad & 1) * 8 + lr) * SROW + (quad >> 1) * 8) * 2;
    const uint32_t boff = (((quad >> 1) * 8 + lr) * SROW + (quad & 1) * 8) * 2;

    const __half* gA = Ah + (size_t)bm * 128 * K;
    const __half* gB = Bh + (size_t)bn * 128 * K;

    int lrow[4], lcb[4];
#pragma unroll
    for (int i = 0; i < 4; i++) { int c = tid + i * 256; lrow[i] = c >> 3; lcb[i] = c & 7; }

    float acc[4][4][4];
#pragma unroll
    for (int mi = 0; mi < 4; mi++)
#pragma unroll
        for (int ni = 0; ni < 4; ni++)
#pragma unroll
            for (int e = 0; e < 4; e++) acc[mi][ni][e] = 0.f;

    const int NT = K / 64;

    auto issue_stage = [&](int kt) {
        const uint32_t dstS = sb + (kt & 1) * W1STAGE_B;
#pragma unroll
        for (int i = 0; i < 4; i++) {
            CP_ASYNC16(dstS + lrow[i] * (SROW * 2) + lcb[i] * 16,
                       gA + (size_t)(kt * 64) + (size_t)lrow[i] * K + lcb[i] * 8);
            CP_ASYNC16(dstS + TILE_B + lrow[i] * (SROW * 2) + lcb[i] * 16,
                       gB + (size_t)(kt * 64) + (size_t)lrow[i] * K + lcb[i] * 8);
        }
        CP_COMMIT();
    };

    issue_stage(0);

    for (int kt = 0; kt < NT; kt++) {
        if (kt + 1 < NT) { issue_stage(kt + 1); CP_WAIT1(); } else { CP_WAIT0(); }
        __syncthreads();

        const uint32_t sA = sb + (kt & 1) * W1STAGE_B;
        const uint32_t sB = sA + TILE_B;

#pragma unroll
        for (int ks = 0; ks < 4; ks++) {
            const uint32_t k0b = (uint32_t)(ks * 16) * 2;
            uint32_t ah[4][4], bh[4][2];
#pragma unroll
            for (int mi = 0; mi < 4; mi++) {
                const uint32_t rbase = (uint32_t)((wm + mi * 16) * SROW) * 2 + k0b;
                ldsm4(ah[mi], sA + rbase + aoff);
            }
#pragma unroll
            for (int np = 0; np < 2; np++) {
                const uint32_t rbase = (uint32_t)((wn + np * 16) * SROW) * 2 + k0b;
                uint32_t rr[4];
                ldsm4(rr, sB + rbase + boff);
                bh[2 * np][0] = rr[0]; bh[2 * np][1] = rr[1];
                bh[2 * np + 1][0] = rr[2]; bh[2 * np + 1][1] = rr[3];
            }
#pragma unroll
            for (int mi = 0; mi < 4; mi++)
#pragma unroll
                for (int ni = 0; ni < 4; ni++)
                    mma16816(acc[mi][ni], ah[mi], bh[ni]);
        }
        __syncthreads();
    }

#pragma unroll
    for (int mi = 0; mi < 4; mi++) {
#pragma unroll
        for (int half_ = 0; half_ < 2; half_++) {
            const int row = bm * 128 + wm + mi * 16 + g + half_ * 8;
#pragma unroll
            for (int ni = 0; ni < 4; ni++) {
                const int c = bn * 128 + wn + ni * 8 + tig * 2;
                float v0 = acc[mi][ni][half_ * 2 + 0];
                float v1 = acc[mi][ni][half_ * 2 + 1];
                if (EPI == 5) {
                    v0 += bias[c]; v1 += bias[c + 1];
                    *(__half2*)&Oh[(size_t)row * N + c] = __floats2half2_rn(v0, v1);
                } else if (EPI == 2) {
                    v0 += bias[c]; v1 += bias[c + 1];
                    *(__half2*)&Oh[(size_t)row * N + c] =
                        __floats2half2_rn(gelu_fast(v0), gelu_fast(v1));
                } else {   // EPI == 4: V scatter
                    const int h = c >> 6;
                    const int d = c & 63;
                    v0 += bias[h * 192 + 128 + d]; v1 += bias[h * 192 + 128 + d + 1];
                    const int b_ = row >> 10, s_ = row & 1023;
                    const size_t base = ((size_t)(b_ * Hh + h) * Sq + s_) * DH;
                    *(__half2*)&vh[base + d] = __floats2half2_rn(v0, v1);
                }
            }
        }
    }
}

// ---------------- tensor-core flash attention (cp.async + ldmatrix, double-buffered) ----
#define ASROW 72
#define AT_H (64 * ASROW)              // 4608 halves per tile
#define AST_B (3 * AT_H * 2)           // 27648 bytes per stage
#define ATT_SMEM (2 * AST_B + 1024)    // + mask

__global__ __launch_bounds__(256, 2)
void attn_mma(const __half* __restrict__ qg, const __half* __restrict__ qlg,
              const __half* __restrict__ kg, const __half* __restrict__ klg,
              const __half* __restrict__ vg, const unsigned char* __restrict__ maskg,
              __half* __restrict__ ctx) {
    extern __shared__ char asmem[];
    const uint32_t sbase = smem_u32(asmem);
    unsigned char* Msall = (unsigned char*)(asmem + 2 * AST_B);

    const int tid = threadIdx.x;
    const int w = tid >> 5, lane = tid & 31;
    const int g = lane >> 2, tig = lane & 3;
    const int quad = lane >> 3, lr = lane & 7;
    const int qblk = blockIdx.x, h = blockIdx.y, b = blockIdx.z;
    const size_t bh = (size_t)(b * Hh + h) * Sq;
    const int qrow0 = qblk * 128 + w * 16;

    const uint32_t boff = (((quad >> 1) * 8 + lr) * ASROW + (quad & 1) * 8) * 2;
    const uint32_t voff = (((quad & 1) * 8 + lr) * ASROW) * 2 + (quad >> 1) * 16;

    *(uchar4*)&Msall[tid * 4] = ((const uchar4*)(maskg + (size_t)b * Sq))[tid];

    uint32_t qfh[4][4], qfl[4][4];
#pragma unroll
    for (int ks = 0; ks < 4; ks++) {
        const int k0 = ks * 16 + tig * 2;
        const size_t r0 = (bh + qrow0 + g) * DH;
        const size_t r1 = (bh + qrow0 + g + 8) * DH;
        qfh[ks][0] = *(const uint32_t*)(qg + r0 + k0);
        qfh[ks][1] = *(const uint32_t*)(qg + r1 + k0);
        qfh[ks][2] = *(const uint32_t*)(qg + r0 + k0 + 8);
        qfh[ks][3] = *(const uint32_t*)(qg + r1 + k0 + 8);
        qfl[ks][0] = *(const uint32_t*)(qlg + r0 + k0);
        qfl[ks][1] = *(const uint32_t*)(qlg + r1 + k0);
        qfl[ks][2] = *(const uint32_t*)(qlg + r0 + k0 + 8);
        qfl[ks][3] = *(const uint32_t*)(qlg + r1 + k0 + 8);
    }

    auto issue_stage = [&](int kt) {
        const uint32_t dst0 = sbase + (kt & 1) * AST_B;
#pragma unroll
        for (int i = 0; i < 6; i++) {
            const int c = tid + i * 256;
            const int t = c >> 9;
            const int cc = c & 511;
            const int row = cc >> 3, col = cc & 7;
            const __half* src = (t == 0 ? kg : (t == 1 ? klg : vg))
                                + (bh + kt * 64 + row) * DH + col * 8;
            CP_ASYNC16(dst0 + t * (AT_H * 2) + row * (ASROW * 2) + col * 16, src);
        }
        CP_COMMIT();
    };

    float out[8][4];
#pragma unroll
    for (int nt = 0; nt < 8; nt++)
#pragma unroll
        for (int e = 0; e < 4; e++) out[nt][e] = 0.f;
    float m0 = -1e30f, m1 = -1e30f, l0 = 0.f, l1 = 0.f;

    issue_stage(0);

    for (int kt = 0; kt < 16; kt++) {
        if (kt + 1 < 16) { issue_stage(kt + 1); CP_WAIT1(); } else { CP_WAIT0(); }
        __syncthreads();

        const uint32_t sK  = sbase + (kt & 1) * AST_B;
        const uint32_t sKl = sK + AT_H * 2;
        const uint32_t sV  = sK + 2 * AT_H * 2;

        float s[8][4];
#pragma unroll
        for (int nt = 0; nt < 8; nt++)
#pragma unroll
            for (int e = 0; e < 4; e++) s[nt][e] = 0.f;
#pragma unroll
        for (int ks = 0; ks < 4; ks++) {
            const uint32_t k0b = (uint32_t)(ks * 16) * 2;
#pragma unroll
            for (int np = 0; np < 4; np++) {
                const uint32_t rbase = (uint32_t)(np * 16 * ASROW) * 2 + k0b;
                uint32_t rh[4], rl[4];
                ldsm4(rh, sK + rbase + boff);
                ldsm4(rl, sKl + rbase + boff);
                mma16816(s[2 * np],     qfh[ks], rh);
                mma16816(s[2 * np],     qfl[ks], rh);
                mma16816(s[2 * np],     qfh[ks], rl);
                mma16816(s[2 * np + 1], qfh[ks], rh + 2);
                mma16816(s[2 * np + 1], qfl[ks], rh + 2);
                mma16816(s[2 * np + 1], qfh[ks], rl + 2);
            }
        }

        const unsigned char* Mt = Msall + kt * 64;
        float mx0 = -1e30f, mx1 = -1e30f;
#pragma unroll
        for (int nt = 0; nt < 8; nt++) {
            const int col = nt * 8 + tig * 2;
            if (Mt[col])     { s[nt][0] = -1e30f; s[nt][2] = -1e30f; }
            if (Mt[col + 1]) { s[nt][1] = -1e30f; s[nt][3] = -1e30f; }
            mx0 = fmaxf(mx0, fmaxf(s[nt][0], s[nt][1]));
            mx1 = fmaxf(mx1, fmaxf(s[nt][2], s[nt][3]));
        }
        mx0 = fmaxf(mx0, __shfl_xor_sync(0xffffffffu, mx0, 1));
        mx0 = fmaxf(mx0, __shfl_xor_sync(0xffffffffu, mx0, 2));
        mx1 = fmaxf(mx1, __shfl_xor_sync(0xffffffffu, mx1, 1));
        mx1 = fmaxf(mx1, __shfl_xor_sync(0xffffffffu, mx1, 2));

        if (mx0 > m0) {
            const float sc0 = __expf(m0 - mx0);
            m0 = mx0;
            l0 *= sc0;
#pragma unroll
            for (int nt = 0; nt < 8; nt++) { out[nt][0] *= sc0; out[nt][1] *= sc0; }
        }
        if (mx1 > m1) {
            const float sc1 = __expf(m1 - mx1);
            m1 = mx1;
            l1 *= sc1;
#pragma unroll
            for (int nt = 0; nt < 8; nt++) { out[nt][2] *= sc1; out[nt][3] *= sc1; }
        }

        float rs0 = 0.f, rs1 = 0.f;
#pragma unroll
        for (int nt = 0; nt < 8; nt++) {
            s[nt][0] = __expf(s[nt][0] - m0);
            s[nt][1] = __expf(s[nt][1] - m0);
            s[nt][2] = __expf(s[nt][2] - m1);
            s[nt][3] = __expf(s[nt][3] - m1);
            rs0 += s[nt][0] + s[nt][1];
            rs1 += s[nt][2] + s[nt][3];
        }
        rs0 += __shfl_xor_sync(0xffffffffu, rs0, 1);
        rs0 += __shfl_xor_sync(0xffffffffu, rs0, 2);
        rs1 += __shfl_xor_sync(0xffffffffu, rs1, 1);
        rs1 += __shfl_xor_sync(0xffffffffu, rs1, 2);
        l0 += rs0;
        l1 += rs1;

#pragma unroll
        for (int kg2 = 0; kg2 < 4; kg2++) {
            uint32_t pa[4];
            pa[0] = packh2(s[2 * kg2][0], s[2 * kg2][1]);
            pa[1] = packh2(s[2 * kg2][2], s[2 * kg2][3]);
            pa[2] = packh2(s[2 * kg2 + 1][0], s[2 * kg2 + 1][1]);
            pa[3] = packh2(s[2 * kg2 + 1][2], s[2 * kg2 + 1][3]);
            const uint32_t kbase = (uint32_t)(kg2 * 16 * ASROW) * 2;
#pragma unroll
            for (int ng = 0; ng < 4; ng++) {
                uint32_t rr[4];
                ldsm4t(rr, sV + kbase + (uint32_t)(ng * 32) + voff);
                mma16816(out[2 * ng],     pa, rr);
                mma16816(out[2 * ng + 1], pa, rr + 2);
            }
        }
        __syncthreads();
    }

    const float i0 = 1.0f / l0, i1 = 1.0f / l1;
    const int r0 = qrow0 + g, r1 = qrow0 + g + 8;
    __half* p0 = ctx + ((size_t)(b * Sq + r0) * Hh + h) * DH;
    __half* p1 = ctx + ((size_t)(b * Sq + r1) * Hh + h) * DH;
#pragma unroll
    for (int nt = 0; nt < 8; nt++) {
        const int dh = nt * 8 + tig * 2;
        *(__half2*)(p0 + dh) = __floats2half2_rn(out[nt][0] * i0, out[nt][1] * i0);
        *(__half2*)(p1 + dh) = __floats2half2_rn(out[nt][2] * i1, out[nt][3] * i1);
    }
}

// ---------------- fused add + LayerNorm (fp32 a + fp16 b; optional fp32/fp16 outs) ----
__global__ __launch_bounds__(256)
void addln_kernel(const float* __restrict__ a, const __half* __restrict__ bhp,
                  const float* __restrict__ g, const float* __restrict__ bt,
                  float* __restrict__ o, __half* __restrict__ oh,
                  float* __restrict__ outf) {
    __shared__ float redS[8], redQ[8], outMV[2];
    const int row = blockIdx.x;
    const int t = threadIdx.x;
    const float* ar = a + (size_t)row * Dm;
    const __half* br = bhp + (size_t)row * Dm;

    float v[4];
    float s = 0.f, sq = 0.f;
#pragma unroll
    for (int i = 0; i < 4; i++) {
        int idx = t + i * 256;
        float x = ar[idx] + __half2float(br[idx]);
        v[i] = x;
        s += x;
        sq = fmaf(x, x, sq);
    }
#pragma unroll
    for (int off = 16; off; off >>= 1) {
        s += __shfl_xor_sync(0xFFFFFFFFu, s, off);
        sq += __shfl_xor_sync(0xFFFFFFFFu, sq, off);
    }
    if ((t & 31) == 0) { redS[t >> 5] = s; redQ[t >> 5] = sq; }
    __syncthreads();
    if (t < 32) {
        float s2 = (t < 8) ? redS[t] : 0.f;
        float q2 = (t < 8) ? redQ[t] : 0.f;
#pragma unroll
        for (int off = 4; off; off >>= 1) {
            s2 += __shfl_xor_sync(0xFFFFFFFFu, s2, off);
            q2 += __shfl_xor_sync(0xFFFFFFFFu, q2, off);
        }
        if (t == 0) {
            float mean = s2 * (1.0f / Dm);
            float var = q2 * (1.0f / Dm) - mean * mean;
            outMV[0] = mean;
            outMV[1] = rsqrtf(var + 1e-5f);
        }
    }
    __syncthreads();
    const float mean = outMV[0], rstd = outMV[1];
#pragma unroll
    for (int i = 0; i < 4; i++) {
        int idx = t + i * 256;
        float y = (v[i] - mean) * rstd * g[idx] + bt[idx];
        if (o)    o[(size_t)row * Dm + idx] = y;
        if (oh)   oh[(size_t)row * Dm + idx] = __float2half_rn(y);
        if (outf) outf[(size_t)row * Dm + idx] = y;
    }
}

// ---------------- launch ----------------
extern "C" void kernel_launch(void* const* d_in, const int* in_sizes, int n_in,
                              void* d_out, int out_size) {
    const float* seq  = (const float*)d_in[0];
    const unsigned char* mask = (const unsigned char*)d_in[1];
    const float* Wqkv = (const float*)d_in[2];
    const float* bqkv = (const float*)d_in[3];
    const float* Wo   = (const float*)d_in[4];
    const float* bo   = (const float*)d_in[5];
    const float* g1   = (const float*)d_in[6];
    const float* b1   = (const float*)d_in[7];
    const float* Wi   = (const float*)d_in[8];
    const float* bi   = (const float*)d_in[9];
    const float* Wout = (const float*)d_in[10];
    const float* bout = (const float*)d_in[11];
    const float* g2   = (const float*)d_in[12];
    const float* b2   = (const float*)d_in[13];
    float* out = (float*)d_out;

    __half *seqh, *seql, *Bqkh, *Bqkl, *Bvh, *Woh, *Wih, *Wouth;
    __half *qh, *ql, *kh, *kl, *vh, *ctxh, *xh, *hh, *attnh, *yh;
    float *x;
    cudaGetSymbolAddress((void**)&seqh, g_seqh);   cudaGetSymbolAddress((void**)&seql, g_seql);
    cudaGetSymbolAddress((void**)&Bqkh, g_Bqkh);   cudaGetSymbolAddress((void**)&Bqkl, g_Bqkl);
    cudaGetSymbolAddress((void**)&Bvh, g_Bvh);
    cudaGetSymbolAddress((void**)&Woh, g_Woh);
    cudaGetSymbolAddress((void**)&Wih, g_Wih);
    cudaGetSymbolAddress((void**)&Wouth, g_Wouth);
    cudaGetSymbolAddress((void**)&qh, g_qh);       cudaGetSymbolAddress((void**)&ql, g_ql);
    cudaGetSymbolAddress((void**)&kh, g_kh);       cudaGetSymbolAddress((void**)&kl, g_kl);
    cudaGetSymbolAddress((void**)&vh, g_vh);       cudaGetSymbolAddress((void**)&ctxh, g_ctxh);
    cudaGetSymbolAddress((void**)&xh, g_xh);       cudaGetSymbolAddress((void**)&hh, g_hh);
    cudaGetSymbolAddress((void**)&attnh, g_attnh); cudaGetSymbolAddress((void**)&x, g_x);
    cudaGetSymbolAddress((void**)&yh, g_yh);

    cudaFuncSetAttribute(mma_gemm_qk,   cudaFuncAttributeMaxDynamicSharedMemorySize, QK_SMEM);
    cudaFuncSetAttribute(mma_gemm_w<4>, cudaFuncAttributeMaxDynamicSharedMemorySize, W1_SMEM);
    cudaFuncSetAttribute(mma_gemm_w<5>, cudaFuncAttributeMaxDynamicSharedMemorySize, W1_SMEM);
    cudaFuncSetAttribute(mma_gemm_w<2>, cudaFuncAttributeMaxDynamicSharedMemorySize, W1_SMEM);
    cudaFuncSetAttribute(attn_mma, cudaFuncAttributeMaxDynamicSharedMemorySize, ATT_SMEM);

    // weight packing
    packW_kernel<<<dim3(4, 32, Hh), dim3(32, 8)>>>(Wqkv, Bqkh, Bqkl, Dm, 192, 0, 128);
    packW_kernel<<<dim3(2, 32, Hh), dim3(32, 8)>>>(Wqkv, Bvh, nullptr, Dm, 192, 128, 64);
    packW_kernel<<<dim3(Dm / 32, Dm / 32, 1), dim3(32, 8)>>>(Wo, Woh, nullptr, Dm, Dm, 0, Dm);
    packW_kernel<<<dim3(Ii / 32, Dm / 32, 1), dim3(32, 8)>>>(Wi, Wih, nullptr, Dm, Ii, 0, Ii);
    packW_kernel<<<dim3(Dm / 32, Ii / 32, 1), dim3(32, 8)>>>(Wout, Wouth, nullptr, Ii, Dm, 0, Dm);

    // seq -> fp16 hi/lo
    split_kernel<<<(ROWS * Dm / 4 + 255) / 256, 256>>>(seq, seqh, seql, ROWS * Dm);

    // QK projection (3-term, 128x64, occ 2) -> q(hi/lo)*8, k(hi/lo)
    mma_gemm_qk<<<dim3(2048 / 64, ROWS / 128), 256, QK_SMEM>>>(
        seqh, seql, Bqkh, Bqkl, bqkv, qh, ql, kh, kl, Dm, 2048);

    // V projection (1-term) -> v fp16
    mma_gemm_w<4><<<dim3(1024 / 128, ROWS / 128), 256, W1_SMEM>>>(
        seqh, Bvh, bqkv, vh, nullptr, Dm, 1024);

    // tensor-core flash attention -> ctx fp16
    attn_mma<<<dim3(8, Hh, Bz), 256, ATT_SMEM>>>(qh, ql, kh, kl, vh, mask, ctxh);

    // output projection (1-term) -> attn fp16
    mma_gemm_w<5><<<dim3(1024 / 128, ROWS / 128), 256, W1_SMEM>>>(
        ctxh, Woh, bo, nullptr, attnh, Dm, 1024);

    // x = LN(seq + attn) -> x fp32 + xh fp16
    addln_kernel<<<ROWS, 256>>>(seq, attnh, g1, b1, x, xh, nullptr);

    // h = gelu(x @ Wi + bi) (1-term, fast erf) -> fp16
    mma_gemm_w<2><<<dim3(Ii / 128, ROWS / 128), 256, W1_SMEM>>>(
        xh, Wih, bi, nullptr, hh, Dm, Ii);

    // y = h @ Wout + bout (1-term) -> fp16
    mma_gemm_w<5><<<dim3(1024 / 128, ROWS / 128), 256, W1_SMEM>>>(
        hh, Wouth, bout, nullptr, yh, Ii, 1024);

    // out = LN(x + y)
    addln_kernel<<<ROWS, 256>>>(x, yh, g2, b2, nullptr, nullptr, out);
}

// round 16
// speedup vs baseline: 1.5427x; 1.5427x over previous
#include <cuda_runtime.h>
#include <cuda_fp16.h>
#include <math.h>
#include <stdint.h>

#define Bz 8
#define Sq 1024
#define Dm 1024
#define Hh 16
#define DH 64
#define Ii 4096
#define ROWS (Bz * Sq)

// ---------------- scratch (static device memory; no allocations) ----------------
__device__ __half g_seqh[ROWS * Dm], g_seql[ROWS * Dm];
__device__ __half g_Bqkh[2048 * Dm], g_Bqkl[2048 * Dm];
__device__ __half g_Bvh[1024 * Dm];
__device__ __half g_Woh[Dm * Dm];
__device__ __half g_Wih[Ii * Dm];
__device__ __half g_Wouth[Dm * Ii];
__device__ __half g_qh[ROWS * Dm], g_ql[ROWS * Dm];
__device__ __half g_kh[ROWS * Dm], g_kl[ROWS * Dm];
__device__ __half g_vh[ROWS * Dm];
__device__ __half g_ctxh[ROWS * Dm];
__device__ __half g_attnh[ROWS * Dm];
__device__ float g_x[ROWS * Dm];
__device__ __half g_xh[ROWS * Dm];
__device__ __half g_hh[ROWS * Ii];
__device__ __half g_yh[ROWS * Dm];

// ---------------- helpers ----------------
__device__ __forceinline__ uint32_t smem_u32(const void* p) {
    uint32_t r;
    asm("{ .reg .u64 t; cvta.to.shared.u64 t, %1; cvt.u32.u64 %0, t; }" : "=r"(r) : "l"(p));
    return r;
}
#define CP_ASYNC16(dst, src) \
    asm volatile("cp.async.cg.shared.global [%0], [%1], 16;" :: "r"(dst), "l"(src) : "memory")
#define CP_COMMIT() asm volatile("cp.async.commit_group;" ::: "memory")
#define CP_WAIT1()  asm volatile("cp.async.wait_group 1;" ::: "memory")
#define CP_WAIT0()  asm volatile("cp.async.wait_group 0;" ::: "memory")

__device__ __forceinline__ void mma16816(float* d, const uint32_t* a, const uint32_t* b) {
    asm volatile(
        "mma.sync.aligned.m16n8k16.row.col.f32.f16.f16.f32 "
        "{%0,%1,%2,%3}, {%4,%5,%6,%7}, {%8,%9}, {%0,%1,%2,%3};"
        : "+f"(d[0]), "+f"(d[1]), "+f"(d[2]), "+f"(d[3])
        : "r"(a[0]), "r"(a[1]), "r"(a[2]), "r"(a[3]), "r"(b[0]), "r"(b[1]));
}
__device__ __forceinline__ void ldsm4(uint32_t* r, uint32_t a) {
    asm volatile("ldmatrix.sync.aligned.m8n8.x4.shared.b16 {%0,%1,%2,%3}, [%4];"
                 : "=r"(r[0]), "=r"(r[1]), "=r"(r[2]), "=r"(r[3]) : "r"(a));
}
__device__ __forceinline__ void ldsm4t(uint32_t* r, uint32_t a) {
    asm volatile("ldmatrix.sync.aligned.m8n8.x4.trans.shared.b16 {%0,%1,%2,%3}, [%4];"
                 : "=r"(r[0]), "=r"(r[1]), "=r"(r[2]), "=r"(r[3]) : "r"(a));
}
__device__ __forceinline__ uint32_t packh2(float a, float b) {
    __half2 h = __floats2half2_rn(a, b);
    return *(uint32_t*)&h;
}
// Branch-free erf, Abramowitz-Stegun 7.1.26 (|err| <= 1.5e-7)
__device__ __forceinline__ float erf_fast(float x) {
    float ax = fabsf(x);
    float t = __fdividef(1.0f, fmaf(0.3275911f, ax, 1.0f));
    float p = t * fmaf(t, fmaf(t, fmaf(t, fmaf(t, 1.061405429f, -1.453152027f),
                                       1.421413741f), -0.284496736f), 0.254829592f);
    float r = 1.0f - p * __expf(-ax * ax);
    return copysignf(r, x);
}
__device__ __forceinline__ float gelu_fast(float v) {
    return 0.5f * v * (1.0f + erf_fast(v * 0.70710678118654752f));
}

// ---------------- weight pack: per-head column window, transpose + fp16 (hi[/lo]) ----
__global__ void packW_kernel(const float* __restrict__ w, __half* __restrict__ oh,
                             __half* __restrict__ ol, int K, int N, int ncol0, int nout) {
    __shared__ float t[32][33];
    const int z = blockIdx.z;
    const float* in = w + (size_t)z * K * N;
    __half* poh = oh + (size_t)z * nout * K;
    __half* pol = ol ? ol + (size_t)z * nout * K : nullptr;
    const int n0 = blockIdx.x * 32, k0 = blockIdx.y * 32;
    const int tx = threadIdx.x, ty = threadIdx.y;
#pragma unroll
    for (int i = 0; i < 32; i += 8)
        t[ty + i][tx] = in[(size_t)(k0 + ty + i) * N + ncol0 + n0 + tx];
    __syncthreads();
#pragma unroll
    for (int i = 0; i < 32; i += 8) {
        float v = t[tx][ty + i];
        __half hi = __float2half_rn(v);
        size_t o = (size_t)(n0 + ty + i) * K + k0 + tx;
        poh[o] = hi;
        if (pol) pol[o] = __float2half_rn(v - __half2float(hi));
    }
}

// ---------------- fp32 -> fp16 hi/lo ----------------
__global__ void split_kernel(const float* __restrict__ in, __half* __restrict__ oh,
                             __half* __restrict__ ol, int n) {
    int i = (blockIdx.x * 256 + threadIdx.x) * 4;
    if (i < n) {
        float4 v = *(const float4*)(in + i);
        __half h0 = __float2half_rn(v.x), h1 = __float2half_rn(v.y);
        __half h2 = __float2half_rn(v.z), h3 = __float2half_rn(v.w);
        __half2* ph = (__half2*)(oh + i);
        ph[0] = __halves2half2(h0, h1);
        ph[1] = __halves2half2(h2, h3);
        __half2* pl = (__half2*)(ol + i);
        pl[0] = __halves2half2(__float2half_rn(v.x - __half2float(h0)),
                               __float2half_rn(v.y - __half2float(h1)));
        pl[1] = __halves2half2(__float2half_rn(v.z - __half2float(h2)),
                               __float2half_rn(v.w - __half2float(h3)));
    }
}

// ---------------- mma.sync GEMM (ldmatrix fragments, 2-stage cp.async) ----------------
// TERMS=3: acc = Ah*Bh + Ah*Bl + Al*Bh ; TERMS=1: acc = A*B
// EPI 2: Oh = fp16(gelu(v + bias[c]))   (fast erf)
// EPI 3: QK scatter (N=2048): c -> h=c>>7, e=c&127; e<64: q*8 hi/lo, else k hi/lo
// EPI 4: V write   (N=1024): c -> h=c>>6, d=c&63 -> vh fp16
// EPI 5: Oh = fp16(v + bias[c])
#define SROW 72
#define TILE_H (128 * SROW)
#define TILE_B (TILE_H * 2)            // 18432 bytes

template <int EPI, int TERMS, int OCC>
__global__ __launch_bounds__(256, OCC)
void mma_gemm(const __half* __restrict__ Ah, const __half* __restrict__ Al,
              const __half* __restrict__ Bh, const __half* __restrict__ Bl,
              const float* __restrict__ bias,
              __half* __restrict__ qh, __half* __restrict__ ql,
              __half* __restrict__ kh, __half* __restrict__ kl,
              __half* __restrict__ vh, __half* __restrict__ Oh,
              int K, int N) {
    constexpr int NTILES = (TERMS == 3) ? 4 : 2;
    constexpr int STAGE_B = NTILES * TILE_B;
    extern __shared__ char smem[];
    const uint32_t sb = smem_u32(smem);
    const int tid = threadIdx.x;
    const int w = tid >> 5, lane = tid & 31;
    const int g = lane >> 2, tig = lane & 3;
    const int quad = lane >> 3, lr = lane & 7;
    const int bm = blockIdx.y, bn = blockIdx.x;
    const int wm = (w >> 2) * 64;
    const int wn = (w & 3) * 32;

    const uint32_t aoff = (((quad & 1) * 8 + lr) * SROW + (quad >> 1) * 8) * 2;
    const uint32_t boff = (((quad >> 1) * 8 + lr) * SROW + (quad & 1) * 8) * 2;

    const __half* gp[4];
    gp[0] = Ah + (size_t)bm * 128 * K;
    if (TERMS == 3) {
        gp[1] = Al + (size_t)bm * 128 * K;
        gp[2] = Bh + (size_t)bn * 128 * K;
        gp[3] = Bl + (size_t)bn * 128 * K;
    } else {
        gp[1] = Bh + (size_t)bn * 128 * K;
    }

    int lrow[4], lcb[4];
#pragma unroll
    for (int i = 0; i < 4; i++) { int c = tid + i * 256; lrow[i] = c >> 3; lcb[i] = c & 7; }

    float acc[4][4][4];
#pragma unroll
    for (int mi = 0; mi < 4; mi++)
#pragma unroll
        for (int ni = 0; ni < 4; ni++)
#pragma unroll
            for (int e = 0; e < 4; e++) acc[mi][ni][e] = 0.f;

    const int NT = K / 64;

    auto issue_stage = [&](int kt) {
        const uint32_t dstS = sb + (kt & 1) * STAGE_B;
#pragma unroll
        for (int t = 0; t < NTILES; t++) {
            const __half* src = gp[t] + kt * 64;
#pragma unroll
            for (int i = 0; i < 4; i++) {
                CP_ASYNC16(dstS + t * TILE_B + lrow[i] * (SROW * 2) + lcb[i] * 16,
                           src + (size_t)lrow[i] * K + lcb[i] * 8);
            }
        }
        CP_COMMIT();
    };

    issue_stage(0);

    for (int kt = 0; kt < NT; kt++) {
        if (kt + 1 < NT) { issue_stage(kt + 1); CP_WAIT1(); } else { CP_WAIT0(); }
        __syncthreads();

        const uint32_t sA  = sb + (kt & 1) * STAGE_B;
        const uint32_t sAl = sA + TILE_B;
        const uint32_t sBh = sA + ((TERMS == 3) ? 2 : 1) * TILE_B;
        const uint32_t sBl = sA + 3 * TILE_B;

#pragma unroll
        for (int ks = 0; ks < 4; ks++) {
            const uint32_t k0b = (uint32_t)(ks * 16) * 2;
            uint32_t ah[4][4], al[4][4], bh[4][2], bl[4][2];
#pragma unroll
            for (int mi = 0; mi < 4; mi++) {
                const uint32_t rbase = (uint32_t)((wm + mi * 16) * SROW) * 2 + k0b;
                ldsm4(ah[mi], sA + rbase + aoff);
                if (TERMS == 3) ldsm4(al[mi], sAl + rbase + aoff);
            }
#pragma unroll
            for (int np = 0; np < 2; np++) {
                const uint32_t rbase = (uint32_t)((wn + np * 16) * SROW) * 2 + k0b;
                uint32_t rr[4];
                ldsm4(rr, sBh + rbase + boff);
                bh[2 * np][0] = rr[0]; bh[2 * np][1] = rr[1];
                bh[2 * np + 1][0] = rr[2]; bh[2 * np + 1][1] = rr[3];
                if (TERMS == 3) {
                    ldsm4(rr, sBl + rbase + boff);
                    bl[2 * np][0] = rr[0]; bl[2 * np][1] = rr[1];
                    bl[2 * np + 1][0] = rr[2]; bl[2 * np + 1][1] = rr[3];
                }
            }
#pragma unroll
            for (int mi = 0; mi < 4; mi++)
#pragma unroll
                for (int ni = 0; ni < 4; ni++) {
                    mma16816(acc[mi][ni], ah[mi], bh[ni]);
                    if (TERMS == 3) {
                        mma16816(acc[mi][ni], ah[mi], bl[ni]);
                        mma16816(acc[mi][ni], al[mi], bh[ni]);
                    }
                }
        }
        __syncthreads();
    }

    // ---------------- epilogue ----------------
#pragma unroll
    for (int mi = 0; mi < 4; mi++) {
#pragma unroll
        for (int half_ = 0; half_ < 2; half_++) {
            const int row = bm * 128 + wm + mi * 16 + g + half_ * 8;
#pragma unroll
            for (int ni = 0; ni < 4; ni++) {
                const int c = bn * 128 + wn + ni * 8 + tig * 2;
                float v0 = acc[mi][ni][half_ * 2 + 0];
                float v1 = acc[mi][ni][half_ * 2 + 1];
                if (EPI == 5) {
                    v0 += bias[c]; v1 += bias[c + 1];
                    *(__half2*)&Oh[(size_t)row * N + c] = __floats2half2_rn(v0, v1);
                } else if (EPI == 2) {
                    v0 += bias[c]; v1 += bias[c + 1];
                    *(__half2*)&Oh[(size_t)row * N + c] =
                        __floats2half2_rn(gelu_fast(v0), gelu_fast(v1));
                } else if (EPI == 3) {
                    const int h = c >> 7;
                    const int e = c & 127;
                    v0 += bias[h * 192 + e]; v1 += bias[h * 192 + e + 1];
                    const int b_ = row >> 10, s_ = row & 1023;
                    const size_t base = ((size_t)(b_ * Hh + h) * Sq + s_) * DH;
                    if (e < DH) {
                        float s0 = v0 * 8.0f, s1 = v1 * 8.0f;   // sqrt(DH)=8
                        __half h0 = __float2half_rn(s0), h1 = __float2half_rn(s1);
                        *(__half2*)&qh[base + e] = __halves2half2(h0, h1);
                        *(__half2*)&ql[base + e] =
                            __halves2half2(__float2half_rn(s0 - __half2float(h0)),
                                           __float2half_rn(s1 - __half2float(h1)));
                    } else {
                        __half h0 = __float2half_rn(v0), h1 = __float2half_rn(v1);
                        *(__half2*)&kh[base + e - DH] = __halves2half2(h0, h1);
                        *(__half2*)&kl[base + e - DH] =
                            __halves2half2(__float2half_rn(v0 - __half2float(h0)),
                                           __float2half_rn(v1 - __half2float(h1)));
                    }
                } else {   // EPI == 4: V
                    const int h = c >> 6;
                    const int d = c & 63;
                    v0 += bias[h * 192 + 128 + d]; v1 += bias[h * 192 + 128 + d + 1];
                    const int b_ = row >> 10, s_ = row & 1023;
                    const size_t base = ((size_t)(b_ * Hh + h) * Sq + s_) * DH;
                    *(__half2*)&vh[base + d] = __floats2half2_rn(v0, v1);
                }
            }
        }
    }
}

// ---------------- tensor-core flash attention (cp.async + ldmatrix, double-buffered) ----
#define ASROW 72
#define AT_H (64 * ASROW)              // 4608 halves per tile
#define AST_B (3 * AT_H * 2)           // 27648 bytes per stage
#define ATT_SMEM (2 * AST_B + 1024)    // + mask

__global__ __launch_bounds__(256, 2)
void attn_mma(const __half* __restrict__ qg, const __half* __restrict__ qlg,
              const __half* __restrict__ kg, const __half* __restrict__ klg,
              const __half* __restrict__ vg, const unsigned char* __restrict__ maskg,
              __half* __restrict__ ctx) {
    extern __shared__ char asmem[];
    const uint32_t sbase = smem_u32(asmem);
    unsigned char* Msall = (unsigned char*)(asmem + 2 * AST_B);

    const int tid = threadIdx.x;
    const int w = tid >> 5, lane = tid & 31;
    const int g = lane >> 2, tig = lane & 3;
    const int quad = lane >> 3, lr = lane & 7;
    const int qblk = blockIdx.x, h = blockIdx.y, b = blockIdx.z;
    const size_t bh = (size_t)(b * Hh + h) * Sq;
    const int qrow0 = qblk * 128 + w * 16;

    const uint32_t boff = (((quad >> 1) * 8 + lr) * ASROW + (quad & 1) * 8) * 2;
    const uint32_t voff = (((quad & 1) * 8 + lr) * ASROW) * 2 + (quad >> 1) * 16;

    *(uchar4*)&Msall[tid * 4] = ((const uchar4*)(maskg + (size_t)b * Sq))[tid];

    uint32_t qfh[4][4], qfl[4][4];
#pragma unroll
    for (int ks = 0; ks < 4; ks++) {
        const int k0 = ks * 16 + tig * 2;
        const size_t r0 = (bh + qrow0 + g) * DH;
        const size_t r1 = (bh + qrow0 + g + 8) * DH;
        qfh[ks][0] = *(const uint32_t*)(qg + r0 + k0);
        qfh[ks][1] = *(const uint32_t*)(qg + r1 + k0);
        qfh[ks][2] = *(const uint32_t*)(qg + r0 + k0 + 8);
        qfh[ks][3] = *(const uint32_t*)(qg + r1 + k0 + 8);
        qfl[ks][0] = *(const uint32_t*)(qlg + r0 + k0);
        qfl[ks][1] = *(const uint32_t*)(qlg + r1 + k0);
        qfl[ks][2] = *(const uint32_t*)(qlg + r0 + k0 + 8);
        qfl[ks][3] = *(const uint32_t*)(qlg + r1 + k0 + 8);
    }

    auto issue_stage = [&](int kt) {
        const uint32_t dst0 = sbase + (kt & 1) * AST_B;
#pragma unroll
        for (int i = 0; i < 6; i++) {
            const int c = tid + i * 256;
            const int t = c >> 9;
            const int cc = c & 511;
            const int row = cc >> 3, col = cc & 7;
            const __half* src = (t == 0 ? kg : (t == 1 ? klg : vg))
                                + (bh + kt * 64 + row) * DH + col * 8;
            CP_ASYNC16(dst0 + t * (AT_H * 2) + row * (ASROW * 2) + col * 16, src);
        }
        CP_COMMIT();
    };

    float out[8][4];
#pragma unroll
    for (int nt = 0; nt < 8; nt++)
#pragma unroll
        for (int e = 0; e < 4; e++) out[nt][e] = 0.f;
    float m0 = -1e30f, m1 = -1e30f, l0 = 0.f, l1 = 0.f;

    issue_stage(0);

    for (int kt = 0; kt < 16; kt++) {
        if (kt + 1 < 16) { issue_stage(kt + 1); CP_WAIT1(); } else { CP_WAIT0(); }
        __syncthreads();

        const uint32_t sK  = sbase + (kt & 1) * AST_B;
        const uint32_t sKl = sK + AT_H * 2;
        const uint32_t sV  = sK + 2 * AT_H * 2;

        float s[8][4];
#pragma unroll
        for (int nt = 0; nt < 8; nt++)
#pragma unroll
            for (int e = 0; e < 4; e++) s[nt][e] = 0.f;
#pragma unroll
        for (int ks = 0; ks < 4; ks++) {
            const uint32_t k0b = (uint32_t)(ks * 16) * 2;
#pragma unroll
            for (int np = 0; np < 4; np++) {
                const uint32_t rbase = (uint32_t)(np * 16 * ASROW) * 2 + k0b;
                uint32_t rh[4], rl[4];
                ldsm4(rh, sK + rbase + boff);
                ldsm4(rl, sKl + rbase + boff);
                mma16816(s[2 * np],     qfh[ks], rh);
                mma16816(s[2 * np],     qfl[ks], rh);
                mma16816(s[2 * np],     qfh[ks], rl);
                mma16816(s[2 * np + 1], qfh[ks], rh + 2);
                mma16816(s[2 * np + 1], qfl[ks], rh + 2);
                mma16816(s[2 * np + 1], qfh[ks], rl + 2);
            }
        }

        const unsigned char* Mt = Msall + kt * 64;
        float mx0 = -1e30f, mx1 = -1e30f;
#pragma unroll
        for (int nt = 0; nt < 8; nt++) {
            const int col = nt * 8 + tig * 2;
            if (Mt[col])     { s[nt][0] = -1e30f; s[nt][2] = -1e30f; }
            if (Mt[col + 1]) { s[nt][1] = -1e30f; s[nt][3] = -1e30f; }
            mx0 = fmaxf(mx0, fmaxf(s[nt][0], s[nt][1]));
            mx1 = fmaxf(mx1, fmaxf(s[nt][2], s[nt][3]));
        }
        mx0 = fmaxf(mx0, __shfl_xor_sync(0xffffffffu, mx0, 1));
        mx0 = fmaxf(mx0, __shfl_xor_sync(0xffffffffu, mx0, 2));
        mx1 = fmaxf(mx1, __shfl_xor_sync(0xffffffffu, mx1, 1));
        mx1 = fmaxf(mx1, __shfl_xor_sync(0xffffffffu, mx1, 2));

        if (mx0 > m0) {
            const float sc0 = __expf(m0 - mx0);
            m0 = mx0;
            l0 *= sc0;
#pragma unroll
            for (int nt = 0; nt < 8; nt++) { out[nt][0] *= sc0; out[nt][1] *= sc0; }
        }
        if (mx1 > m1) {
            const float sc1 = __expf(m1 - mx1);
            m1 = mx1;
            l1 *= sc1;
#pragma unroll
            for (int nt = 0; nt < 8; nt++) { out[nt][2] *= sc1; out[nt][3] *= sc1; }
        }

        float rs0 = 0.f, rs1 = 0.f;
#pragma unroll
        for (int nt = 0; nt < 8; nt++) {
            s[nt][0] = __expf(s[nt][0] - m0);
            s[nt][1] = __expf(s[nt][1] - m0);
            s[nt][2] = __expf(s[nt][2] - m1);
            s[nt][3] = __expf(s[nt][3] - m1);
            rs0 += s[nt][0] + s[nt][1];
            rs1 += s[nt][2] + s[nt][3];
        }
        rs0 += __shfl_xor_sync(0xffffffffu, rs0, 1);
        rs0 += __shfl_xor_sync(0xffffffffu, rs0, 2);
        rs1 += __shfl_xor_sync(0xffffffffu, rs1, 1);
        rs1 += __shfl_xor_sync(0xffffffffu, rs1, 2);
        l0 += rs0;
        l1 += rs1;

#pragma unroll
        for (int kg2 = 0; kg2 < 4; kg2++) {
            uint32_t pa[4];
            pa[0] = packh2(s[2 * kg2][0], s[2 * kg2][1]);
            pa[1] = packh2(s[2 * kg2][2], s[2 * kg2][3]);
            pa[2] = packh2(s[2 * kg2 + 1][0], s[2 * kg2 + 1][1]);
            pa[3] = packh2(s[2 * kg2 + 1][2], s[2 * kg2 + 1][3]);
            const uint32_t kbase = (uint32_t)(kg2 * 16 * ASROW) * 2;
#pragma unroll
            for (int ng = 0; ng < 4; ng++) {
                uint32_t rr[4];
                ldsm4t(rr, sV + kbase + (uint32_t)(ng * 32) + voff);
                mma16816(out[2 * ng],     pa, rr);
                mma16816(out[2 * ng + 1], pa, rr + 2);
            }
        }
        __syncthreads();
    }

    const float i0 = 1.0f / l0, i1 = 1.0f / l1;
    const int r0 = qrow0 + g, r1 = qrow0 + g + 8;
    __half* p0 = ctx + ((size_t)(b * Sq + r0) * Hh + h) * DH;
    __half* p1 = ctx + ((size_t)(b * Sq + r1) * Hh + h) * DH;
#pragma unroll
    for (int nt = 0; nt < 8; nt++) {
        const int dh = nt * 8 + tig * 2;
        *(__half2*)(p0 + dh) = __floats2half2_rn(out[nt][0] * i0, out[nt][1] * i0);
        *(__half2*)(p1 + dh) = __floats2half2_rn(out[nt][2] * i1, out[nt][3] * i1);
    }
}

// ---------------- fused add + LayerNorm (fp32 a + fp16 b; optional fp32/fp16 outs) ----
__global__ __launch_bounds__(256)
void addln_kernel(const float* __restrict__ a, const __half* __restrict__ bhp,
                  const float* __restrict__ g, const float* __restrict__ bt,
                  float* __restrict__ o, __half* __restrict__ oh,
                  float* __restrict__ outf) {
    __shared__ float redS[8], redQ[8], outMV[2];
    const int row = blockIdx.x;
    const int t = threadIdx.x;
    const float* ar = a + (size_t)row * Dm;
    const __half* br = bhp + (size_t)row * Dm;

    float v[4];
    float s = 0.f, sq = 0.f;
#pragma unroll
    for (int i = 0; i < 4; i++) {
        int idx = t + i * 256;
        float x = ar[idx] + __half2float(br[idx]);
        v[i] = x;
        s += x;
        sq = fmaf(x, x, sq);
    }
#pragma unroll
    for (int off = 16; off; off >>= 1) {
        s += __shfl_xor_sync(0xFFFFFFFFu, s, off);
        sq += __shfl_xor_sync(0xFFFFFFFFu, sq, off);
    }
    if ((t & 31) == 0) { redS[t >> 5] = s; redQ[t >> 5] = sq; }
    __syncthreads();
    if (t < 32) {
        float s2 = (t < 8) ? redS[t] : 0.f;
        float q2 = (t < 8) ? redQ[t] : 0.f;
#pragma unroll
        for (int off = 4; off; off >>= 1) {
            s2 += __shfl_xor_sync(0xFFFFFFFFu, s2, off);
            q2 += __shfl_xor_sync(0xFFFFFFFFu, q2, off);
        }
        if (t == 0) {
            float mean = s2 * (1.0f / Dm);
            float var = q2 * (1.0f / Dm) - mean * mean;
            outMV[0] = mean;
            outMV[1] = rsqrtf(var + 1e-5f);
        }
    }
    __syncthreads();
    const float mean = outMV[0], rstd = outMV[1];
#pragma unroll
    for (int i = 0; i < 4; i++) {
        int idx = t + i * 256;
        float y = (v[i] - mean) * rstd * g[idx] + bt[idx];
        if (o)    o[(size_t)row * Dm + idx] = y;
        if (oh)   oh[(size_t)row * Dm + idx] = __float2half_rn(y);
        if (outf) outf[(size_t)row * Dm + idx] = y;
    }
}

// ---------------- launch ----------------
extern "C" void kernel_launch(void* const* d_in, const int* in_sizes, int n_in,
                              void* d_out, int out_size) {
    const float* seq  = (const float*)d_in[0];
    const unsigned char* mask = (const unsigned char*)d_in[1];
    const float* Wqkv = (const float*)d_in[2];
    const float* bqkv = (const float*)d_in[3];
    const float* Wo   = (const float*)d_in[4];
    const float* bo   = (const float*)d_in[5];
    const float* g1   = (const float*)d_in[6];
    const float* b1   = (const float*)d_in[7];
    const float* Wi   = (const float*)d_in[8];
    const float* bi   = (const float*)d_in[9];
    const float* Wout = (const float*)d_in[10];
    const float* bout = (const float*)d_in[11];
    const float* g2   = (const float*)d_in[12];
    const float* b2   = (const float*)d_in[13];
    float* out = (float*)d_out;

    __half *seqh, *seql, *Bqkh, *Bqkl, *Bvh, *Woh, *Wih, *Wouth;
    __half *qh, *ql, *kh, *kl, *vh, *ctxh, *xh, *hh, *attnh, *yh;
    float *x;
    cudaGetSymbolAddress((void**)&seqh, g_seqh);   cudaGetSymbolAddress((void**)&seql, g_seql);
    cudaGetSymbolAddress((void**)&Bqkh, g_Bqkh);   cudaGetSymbolAddress((void**)&Bqkl, g_Bqkl);
    cudaGetSymbolAddress((void**)&Bvh, g_Bvh);
    cudaGetSymbolAddress((void**)&Woh, g_Woh);
    cudaGetSymbolAddress((void**)&Wih, g_Wih);
    cudaGetSymbolAddress((void**)&Wouth, g_Wouth);
    cudaGetSymbolAddress((void**)&qh, g_qh);       cudaGetSymbolAddress((void**)&ql, g_ql);
    cudaGetSymbolAddress((void**)&kh, g_kh);       cudaGetSymbolAddress((void**)&kl, g_kl);
    cudaGetSymbolAddress((void**)&vh, g_vh);       cudaGetSymbolAddress((void**)&ctxh, g_ctxh);
    cudaGetSymbolAddress((void**)&xh, g_xh);       cudaGetSymbolAddress((void**)&hh, g_hh);
    cudaGetSymbolAddress((void**)&attnh, g_attnh); cudaGetSymbolAddress((void**)&x, g_x);
    cudaGetSymbolAddress((void**)&yh, g_yh);

    const int SM3 = 2 * 4 * TILE_B;   // 147456
    const int SM1 = 2 * 2 * TILE_B;   // 73728
    cudaFuncSetAttribute(mma_gemm<3, 3, 1>, cudaFuncAttributeMaxDynamicSharedMemorySize, SM3);
    cudaFuncSetAttribute(mma_gemm<4, 1, 2>, cudaFuncAttributeMaxDynamicSharedMemorySize, SM1);
    cudaFuncSetAttribute(mma_gemm<5, 1, 2>, cudaFuncAttributeMaxDynamicSharedMemorySize, SM1);
    cudaFuncSetAttribute(mma_gemm<2, 1, 2>, cudaFuncAttributeMaxDynamicSharedMemorySize, SM1);
    cudaFuncSetAttribute(attn_mma, cudaFuncAttributeMaxDynamicSharedMemorySize, ATT_SMEM);

    // weight packing
    packW_kernel<<<dim3(4, 32, Hh), dim3(32, 8)>>>(Wqkv, Bqkh, Bqkl, Dm, 192, 0, 128);
    packW_kernel<<<dim3(2, 32, Hh), dim3(32, 8)>>>(Wqkv, Bvh, nullptr, Dm, 192, 128, 64);
    packW_kernel<<<dim3(Dm / 32, Dm / 32, 1), dim3(32, 8)>>>(Wo, Woh, nullptr, Dm, Dm, 0, Dm);
    packW_kernel<<<dim3(Ii / 32, Dm / 32, 1), dim3(32, 8)>>>(Wi, Wih, nullptr, Dm, Ii, 0, Ii);
    packW_kernel<<<dim3(Dm / 32, Ii / 32, 1), dim3(32, 8)>>>(Wout, Wouth, nullptr, Ii, Dm, 0, Dm);

    // seq -> fp16 hi/lo
    split_kernel<<<(ROWS * Dm / 4 + 255) / 256, 256>>>(seq, seqh, seql, ROWS * Dm);

    // QK projection (3-term) -> q(hi/lo)*8, k(hi/lo)
    mma_gemm<3, 3, 1><<<dim3(2048 / 128, ROWS / 128), 256, SM3>>>(
        seqh, seql, Bqkh, Bqkl, bqkv, qh, ql, kh, kl, nullptr, nullptr, Dm, 2048);

    // V projection (1-term) -> v fp16
    mma_gemm<4, 1, 2><<<dim3(1024 / 128, ROWS / 128), 256, SM1>>>(
        seqh, nullptr, Bvh, nullptr, bqkv,
        nullptr, nullptr, nullptr, nullptr, vh, nullptr, Dm, 1024);

    // tensor-core flash attention -> ctx fp16
    attn_mma<<<dim3(8, Hh, Bz), 256, ATT_SMEM>>>(qh, ql, kh, kl, vh, mask, ctxh);

    // output projection (1-term) -> attn fp16
    mma_gemm<5, 1, 2><<<dim3(Dm / 128, ROWS / 128), 256, SM1>>>(
        ctxh, nullptr, Woh, nullptr, bo,
        nullptr, nullptr, nullptr, nullptr, nullptr, attnh, Dm, Dm);

    // x = LN(seq + attn) -> x fp32 + xh fp16
    addln_kernel<<<ROWS, 256>>>(seq, attnh, g1, b1, x, xh, nullptr);

    // h = gelu(x @ Wi + bi) (1-term, fast erf) -> fp16
    mma_gemm<2, 1, 2><<<dim3(Ii / 128, ROWS / 128), 256, SM1>>>(
        xh, nullptr, Wih, nullptr, bi,
        nullptr, nullptr, nullptr, nullptr, nullptr, hh, Dm, Ii);

    // y = h @ Wout + bout (1-term) -> fp16
    mma_gemm<5, 1, 2><<<dim3(Dm / 128, ROWS / 128), 256, SM1>>>(
        hh, nullptr, Wouth, nullptr, bout,
        nullptr, nullptr, nullptr, nullptr, nullptr, yh, Ii, Dm);

    // out = LN(x + y)
    addln_kernel<<<ROWS, 256>>>(x, yh, g2, b2, nullptr, nullptr, out);
}

// round 17
// speedup vs baseline: 1.5479x; 1.0034x over previous
#include <cuda_runtime.h>
#include <cuda_fp16.h>
#include <math.h>
#include <stdint.h>

#define Bz 8
#define Sq 1024
#define Dm 1024
#define Hh 16
#define DH 64
#define Ii 4096
#define ROWS (Bz * Sq)

// ---------------- scratch (static device memory; no allocations) ----------------
__device__ __half g_seqh[ROWS * Dm], g_seql[ROWS * Dm];
__device__ __half g_Bqkh[2048 * Dm], g_Bqkl[2048 * Dm];
__device__ __half g_Bvh[1024 * Dm];
__device__ __half g_Woh[Dm * Dm];
__device__ __half g_Wih[Ii * Dm];
__device__ __half g_Wouth[Dm * Ii];
__device__ __half g_qh[ROWS * Dm], g_ql[ROWS * Dm];
__device__ __half g_kh[ROWS * Dm], g_kl[ROWS * Dm];
__device__ __half g_vh[ROWS * Dm];
__device__ __half g_ctxh[ROWS * Dm];
__device__ __half g_attnh[ROWS * Dm];
__device__ float g_x[ROWS * Dm];
__device__ __half g_xh[ROWS * Dm];
__device__ __half g_hh[ROWS * Ii];
__device__ __half g_yh[ROWS * Dm];

// ---------------- helpers ----------------
__device__ __forceinline__ uint32_t smem_u32(const void* p) {
    uint32_t r;
    asm("{ .reg .u64 t; cvta.to.shared.u64 t, %1; cvt.u32.u64 %0, t; }" : "=r"(r) : "l"(p));
    return r;
}
#define CP_ASYNC16(dst, src) \
    asm volatile("cp.async.cg.shared.global [%0], [%1], 16;" :: "r"(dst), "l"(src) : "memory")
#define CP_COMMIT() asm volatile("cp.async.commit_group;" ::: "memory")
#define CP_WAIT1()  asm volatile("cp.async.wait_group 1;" ::: "memory")
#define CP_WAIT0()  asm volatile("cp.async.wait_group 0;" ::: "memory")

__device__ __forceinline__ void mma16816(float* d, const uint32_t* a, const uint32_t* b) {
    asm volatile(
        "mma.sync.aligned.m16n8k16.row.col.f32.f16.f16.f32 "
        "{%0,%1,%2,%3}, {%4,%5,%6,%7}, {%8,%9}, {%0,%1,%2,%3};"
        : "+f"(d[0]), "+f"(d[1]), "+f"(d[2]), "+f"(d[3])
        : "r"(a[0]), "r"(a[1]), "r"(a[2]), "r"(a[3]), "r"(b[0]), "r"(b[1]));
}
__device__ __forceinline__ void ldsm4(uint32_t* r, uint32_t a) {
    asm volatile("ldmatrix.sync.aligned.m8n8.x4.shared.b16 {%0,%1,%2,%3}, [%4];"
                 : "=r"(r[0]), "=r"(r[1]), "=r"(r[2]), "=r"(r[3]) : "r"(a));
}
__device__ __forceinline__ void ldsm4t(uint32_t* r, uint32_t a) {
    asm volatile("ldmatrix.sync.aligned.m8n8.x4.trans.shared.b16 {%0,%1,%2,%3}, [%4];"
                 : "=r"(r[0]), "=r"(r[1]), "=r"(r[2]), "=r"(r[3]) : "r"(a));
}
__device__ __forceinline__ uint32_t packh2(float a, float b) {
    __half2 h = __floats2half2_rn(a, b);
    return *(uint32_t*)&h;
}
// Branch-free erf, Abramowitz-Stegun 7.1.26 (|err| <= 1.5e-7)
__device__ __forceinline__ float erf_fast(float x) {
    float ax = fabsf(x);
    float t = __fdividef(1.0f, fmaf(0.3275911f, ax, 1.0f));
    float p = t * fmaf(t, fmaf(t, fmaf(t, fmaf(t, 1.061405429f, -1.453152027f),
                                       1.421413741f), -0.284496736f), 0.254829592f);
    float r = 1.0f - p * __expf(-ax * ax);
    return copysignf(r, x);
}
__device__ __forceinline__ float gelu_fast(float v) {
    return 0.5f * v * (1.0f + erf_fast(v * 0.70710678118654752f));
}

// ---------------- fused prologue: all weight packs + seq hi/lo split in ONE launch ----
// block ranges:
//   [0,2048)      Wqkv cols [0,128)  -> Bqk hi/lo   (gx=4,  K=1024, heads z)
//   [2048,3072)   Wqkv cols [128,192)-> Bv          (gx=2,  K=1024, heads z)
//   [3072,4096)   Wo  -> Woh                         (gx=32, K=1024)
//   [4096,8192)   Wi  -> Wih                         (gx=128,K=1024)
//   [8192,12288)  Wout-> Wouth                       (gx=32, K=4096)
//   [12288,20480) seq -> seqh/seql (1024 floats per block)
#define PRO_BLOCKS 20480
__global__ __launch_bounds__(256)
void prologue_kernel(const float* __restrict__ Wqkv, const float* __restrict__ Wo,
                     const float* __restrict__ Wi, const float* __restrict__ Wout,
                     const float* __restrict__ seq,
                     __half* __restrict__ Bqkh, __half* __restrict__ Bqkl,
                     __half* __restrict__ Bvh, __half* __restrict__ Woh,
                     __half* __restrict__ Wih, __half* __restrict__ Wouth,
                     __half* __restrict__ seqh, __half* __restrict__ seql) {
    const int bx = blockIdx.x;
    const int tid = threadIdx.x;

    if (bx >= 12288) {
        // -------- seq split: 1024 floats per block --------
        int i = (bx - 12288) * 1024 + tid * 4;
        float4 v = *(const float4*)(seq + i);
        __half h0 = __float2half_rn(v.x), h1 = __float2half_rn(v.y);
        __half h2 = __float2half_rn(v.z), h3 = __float2half_rn(v.w);
        __half2* ph = (__half2*)(seqh + i);
        ph[0] = __halves2half2(h0, h1);
        ph[1] = __halves2half2(h2, h3);
        __half2* pl = (__half2*)(seql + i);
        pl[0] = __halves2half2(__float2half_rn(v.x - __half2float(h0)),
                               __float2half_rn(v.y - __half2float(h1)));
        pl[1] = __halves2half2(__float2half_rn(v.z - __half2float(h2)),
                               __float2half_rn(v.w - __half2float(h3)));
        return;
    }

    // -------- weight pack: transpose 32x32 tile + fp16 (hi[/lo]) --------
    const float* w;
    __half *oh, *ol;
    int K, N, ncol0, nout, gx, base;
    if (bx < 2048)      { w = Wqkv; oh = Bqkh; ol = Bqkl;    K = Dm; N = 192; ncol0 = 0;   nout = 128;  gx = 4;   base = 0; }
    else if (bx < 3072) { w = Wqkv; oh = Bvh;  ol = nullptr; K = Dm; N = 192; ncol0 = 128; nout = 64;   gx = 2;   base = 2048; }
    else if (bx < 4096) { w = Wo;   oh = Woh;  ol = nullptr; K = Dm; N = Dm;  ncol0 = 0;   nout = Dm;   gx = 32;  base = 3072; }
    else if (bx < 8192) { w = Wi;   oh = Wih;  ol = nullptr; K = Dm; N = Ii;  ncol0 = 0;   nout = Ii;   gx = 128; base = 4096; }
    else                { w = Wout; oh = Wouth; ol = nullptr; K = Ii; N = Dm;  ncol0 = 0;   nout = Dm;   gx = 32;  base = 8192; }

    const int local = bx - base;
    const int perz = gx * (K / 32);
    const int z = local / perz;
    const int rem = local - z * perz;
    const int y = rem / gx, xx = rem - (rem / gx) * gx;
    const int n0 = xx * 32, k0 = y * 32;
    const int tx = tid & 31, ty = tid >> 5;

    __shared__ float t[32][33];
    const float* in = w + (size_t)z * K * N;
    __half* poh = oh + (size_t)z * nout * K;
    __half* pol = ol ? ol + (size_t)z * nout * K : nullptr;
#pragma unroll
    for (int i = 0; i < 32; i += 8)
        t[ty + i][tx] = in[(size_t)(k0 + ty + i) * N + ncol0 + n0 + tx];
    __syncthreads();
#pragma unroll
    for (int i = 0; i < 32; i += 8) {
        float v = t[tx][ty + i];
        __half hi = __float2half_rn(v);
        size_t o = (size_t)(n0 + ty + i) * K + k0 + tx;
        poh[o] = hi;
        if (pol) pol[o] = __float2half_rn(v - __half2float(hi));
    }
}

// ---------------- mma.sync GEMM (ldmatrix fragments, 2-stage cp.async) ----------------
// TERMS=3: acc = Ah*Bh + Ah*Bl + Al*Bh ; TERMS=1: acc = A*B
// EPI 2: Oh = fp16(gelu(v + bias[c]))   (fast erf)
// EPI 3: QK scatter (N=2048): c -> h=c>>7, e=c&127; e<64: q*8 hi/lo, else k hi/lo
// EPI 4: V write   (N=1024): c -> h=c>>6, d=c&63 -> vh fp16
// EPI 5: Oh = fp16(v + bias[c])
#define SROW 72
#define TILE_H (128 * SROW)
#define TILE_B (TILE_H * 2)            // 18432 bytes

template <int EPI, int TERMS, int OCC>
__global__ __launch_bounds__(256, OCC)
void mma_gemm(const __half* __restrict__ Ah, const __half* __restrict__ Al,
              const __half* __restrict__ Bh, const __half* __restrict__ Bl,
              const float* __restrict__ bias,
              __half* __restrict__ qh, __half* __restrict__ ql,
              __half* __restrict__ kh, __half* __restrict__ kl,
              __half* __restrict__ vh, __half* __restrict__ Oh,
              int K, int N) {
    constexpr int NTILES = (TERMS == 3) ? 4 : 2;
    constexpr int STAGE_B = NTILES * TILE_B;
    extern __shared__ char smem[];
    const uint32_t sb = smem_u32(smem);
    const int tid = threadIdx.x;
    const int w = tid >> 5, lane = tid & 31;
    const int g = lane >> 2, tig = lane & 3;
    const int quad = lane >> 3, lr = lane & 7;
    const int bm = blockIdx.y, bn = blockIdx.x;
    const int wm = (w >> 2) * 64;
    const int wn = (w & 3) * 32;

    const uint32_t aoff = (((quad & 1) * 8 + lr) * SROW + (quad >> 1) * 8) * 2;
    const uint32_t boff = (((quad >> 1) * 8 + lr) * SROW + (quad & 1) * 8) * 2;

    const __half* gp[4];
    gp[0] = Ah + (size_t)bm * 128 * K;
    if (TERMS == 3) {
        gp[1] = Al + (size_t)bm * 128 * K;
        gp[2] = Bh + (size_t)bn * 128 * K;
        gp[3] = Bl + (size_t)bn * 128 * K;
    } else {
        gp[1] = Bh + (size_t)bn * 128 * K;
    }

    int lrow[4], lcb[4];
#pragma unroll
    for (int i = 0; i < 4; i++) { int c = tid + i * 256; lrow[i] = c >> 3; lcb[i] = c & 7; }

    float acc[4][4][4];
#pragma unroll
    for (int mi = 0; mi < 4; mi++)
#pragma unroll
        for (int ni = 0; ni < 4; ni++)
#pragma unroll
            for (int e = 0; e < 4; e++) acc[mi][ni][e] = 0.f;

    const int NT = K / 64;

    auto issue_stage = [&](int kt) {
        const uint32_t dstS = sb + (kt & 1) * STAGE_B;
#pragma unroll
        for (int t = 0; t < NTILES; t++) {
            const __half* src = gp[t] + kt * 64;
#pragma unroll
            for (int i = 0; i < 4; i++) {
                CP_ASYNC16(dstS + t * TILE_B + lrow[i] * (SROW * 2) + lcb[i] * 16,
                           src + (size_t)lrow[i] * K + lcb[i] * 8);
            }
        }
        CP_COMMIT();
    };

    issue_stage(0);

    for (int kt = 0; kt < NT; kt++) {
        if (kt + 1 < NT) { issue_stage(kt + 1); CP_WAIT1(); } else { CP_WAIT0(); }
        __syncthreads();

        const uint32_t sA  = sb + (kt & 1) * STAGE_B;
        const uint32_t sAl = sA + TILE_B;
        const uint32_t sBh = sA + ((TERMS == 3) ? 2 : 1) * TILE_B;
        const uint32_t sBl = sA + 3 * TILE_B;

#pragma unroll
        for (int ks = 0; ks < 4; ks++) {
            const uint32_t k0b = (uint32_t)(ks * 16) * 2;
            uint32_t ah[4][4], al[4][4], bh[4][2], bl[4][2];
#pragma unroll
            for (int mi = 0; mi < 4; mi++) {
                const uint32_t rbase = (uint32_t)((wm + mi * 16) * SROW) * 2 + k0b;
                ldsm4(ah[mi], sA + rbase + aoff);
                if (TERMS == 3) ldsm4(al[mi], sAl + rbase + aoff);
            }
#pragma unroll
            for (int np = 0; np < 2; np++) {
                const uint32_t rbase = (uint32_t)((wn + np * 16) * SROW) * 2 + k0b;
                uint32_t rr[4];
                ldsm4(rr, sBh + rbase + boff);
                bh[2 * np][0] = rr[0]; bh[2 * np][1] = rr[1];
                bh[2 * np + 1][0] = rr[2]; bh[2 * np + 1][1] = rr[3];
                if (TERMS == 3) {
                    ldsm4(rr, sBl + rbase + boff);
                    bl[2 * np][0] = rr[0]; bl[2 * np][1] = rr[1];
                    bl[2 * np + 1][0] = rr[2]; bl[2 * np + 1][1] = rr[3];
                }
            }
#pragma unroll
            for (int mi = 0; mi < 4; mi++)
#pragma unroll
                for (int ni = 0; ni < 4; ni++) {
                    mma16816(acc[mi][ni], ah[mi], bh[ni]);
                    if (TERMS == 3) {
                        mma16816(acc[mi][ni], ah[mi], bl[ni]);
                        mma16816(acc[mi][ni], al[mi], bh[ni]);
                    }
                }
        }
        __syncthreads();
    }

    // ---------------- epilogue ----------------
#pragma unroll
    for (int mi = 0; mi < 4; mi++) {
#pragma unroll
        for (int half_ = 0; half_ < 2; half_++) {
            const int row = bm * 128 + wm + mi * 16 + g + half_ * 8;
#pragma unroll
            for (int ni = 0; ni < 4; ni++) {
                const int c = bn * 128 + wn + ni * 8 + tig * 2;
                float v0 = acc[mi][ni][half_ * 2 + 0];
                float v1 = acc[mi][ni][half_ * 2 + 1];
                if (EPI == 5) {
                    v0 += bias[c]; v1 += bias[c + 1];
                    *(__half2*)&Oh[(size_t)row * N + c] = __floats2half2_rn(v0, v1);
                } else if (EPI == 2) {
                    v0 += bias[c]; v1 += bias[c + 1];
                    *(__half2*)&Oh[(size_t)row * N + c] =
                        __floats2half2_rn(gelu_fast(v0), gelu_fast(v1));
                } else if (EPI == 3) {
                    const int h = c >> 7;
                    const int e = c & 127;
                    v0 += bias[h * 192 + e]; v1 += bias[h * 192 + e + 1];
                    const int b_ = row >> 10, s_ = row & 1023;
                    const size_t base = ((size_t)(b_ * Hh + h) * Sq + s_) * DH;
                    if (e < DH) {
                        float s0 = v0 * 8.0f, s1 = v1 * 8.0f;   // sqrt(DH)=8
                        __half h0 = __float2half_rn(s0), h1 = __float2half_rn(s1);
                        *(__half2*)&qh[base + e] = __halves2half2(h0, h1);
                        *(__half2*)&ql[base + e] =
                            __halves2half2(__float2half_rn(s0 - __half2float(h0)),
                                           __float2half_rn(s1 - __half2float(h1)));
                    } else {
                        __half h0 = __float2half_rn(v0), h1 = __float2half_rn(v1);
                        *(__half2*)&kh[base + e - DH] = __halves2half2(h0, h1);
                        *(__half2*)&kl[base + e - DH] =
                            __halves2half2(__float2half_rn(v0 - __half2float(h0)),
                                           __float2half_rn(v1 - __half2float(h1)));
                    }
                } else {   // EPI == 4: V
                    const int h = c >> 6;
                    const int d = c & 63;
                    v0 += bias[h * 192 + 128 + d]; v1 += bias[h * 192 + 128 + d + 1];
                    const int b_ = row >> 10, s_ = row & 1023;
                    const size_t base = ((size_t)(b_ * Hh + h) * Sq + s_) * DH;
                    *(__half2*)&vh[base + d] = __floats2half2_rn(v0, v1);
                }
            }
        }
    }
}

// ---------------- tensor-core flash attention (cp.async + ldmatrix, double-buffered) ----
#define ASROW 72
#define AT_H (64 * ASROW)              // 4608 halves per tile
#define AST_B (3 * AT_H * 2)           // 27648 bytes per stage
#define ATT_SMEM (2 * AST_B + 1024)    // + mask

__global__ __launch_bounds__(256, 2)
void attn_mma(const __half* __restrict__ qg, const __half* __restrict__ qlg,
              const __half* __restrict__ kg, const __half* __restrict__ klg,
              const __half* __restrict__ vg, const unsigned char* __restrict__ maskg,
              __half* __restrict__ ctx) {
    extern __shared__ char asmem[];
    const uint32_t sbase = smem_u32(asmem);
    unsigned char* Msall = (unsigned char*)(asmem + 2 * AST_B);

    const int tid = threadIdx.x;
    const int w = tid >> 5, lane = tid & 31;
    const int g = lane >> 2, tig = lane & 3;
    const int quad = lane >> 3, lr = lane & 7;
    const int qblk = blockIdx.x, h = blockIdx.y, b = blockIdx.z;
    const size_t bh = (size_t)(b * Hh + h) * Sq;
    const int qrow0 = qblk * 128 + w * 16;

    const uint32_t boff = (((quad >> 1) * 8 + lr) * ASROW + (quad & 1) * 8) * 2;
    const uint32_t voff = (((quad & 1) * 8 + lr) * ASROW) * 2 + (quad >> 1) * 16;

    *(uchar4*)&Msall[tid * 4] = ((const uchar4*)(maskg + (size_t)b * Sq))[tid];

    uint32_t qfh[4][4], qfl[4][4];
#pragma unroll
    for (int ks = 0; ks < 4; ks++) {
        const int k0 = ks * 16 + tig * 2;
        const size_t r0 = (bh + qrow0 + g) * DH;
        const size_t r1 = (bh + qrow0 + g + 8) * DH;
        qfh[ks][0] = *(const uint32_t*)(qg + r0 + k0);
        qfh[ks][1] = *(const uint32_t*)(qg + r1 + k0);
        qfh[ks][2] = *(const uint32_t*)(qg + r0 + k0 + 8);
        qfh[ks][3] = *(const uint32_t*)(qg + r1 + k0 + 8);
        qfl[ks][0] = *(const uint32_t*)(qlg + r0 + k0);
        qfl[ks][1] = *(const uint32_t*)(qlg + r1 + k0);
        qfl[ks][2] = *(const uint32_t*)(qlg + r0 + k0 + 8);
        qfl[ks][3] = *(const uint32_t*)(qlg + r1 + k0 + 8);
    }

    auto issue_stage = [&](int kt) {
        const uint32_t dst0 = sbase + (kt & 1) * AST_B;
#pragma unroll
        for (int i = 0; i < 6; i++) {
            const int c = tid + i * 256;
            const int t = c >> 9;
            const int cc = c & 511;
            const int row = cc >> 3, col = cc & 7;
            const __half* src = (t == 0 ? kg : (t == 1 ? klg : vg))
                                + (bh + kt * 64 + row) * DH + col * 8;
            CP_ASYNC16(dst0 + t * (AT_H * 2) + row * (ASROW * 2) + col * 16, src);
        }
        CP_COMMIT();
    };

    float out[8][4];
#pragma unroll
    for (int nt = 0; nt < 8; nt++)
#pragma unroll
        for (int e = 0; e < 4; e++) out[nt][e] = 0.f;
    float m0 = -1e30f, m1 = -1e30f, l0 = 0.f, l1 = 0.f;

    issue_stage(0);

    for (int kt = 0; kt < 16; kt++) {
        if (kt + 1 < 16) { issue_stage(kt + 1); CP_WAIT1(); } else { CP_WAIT0(); }
        __syncthreads();

        const uint32_t sK  = sbase + (kt & 1) * AST_B;
        const uint32_t sKl = sK + AT_H * 2;
        const uint32_t sV  = sK + 2 * AT_H * 2;

        float s[8][4];
#pragma unroll
        for (int nt = 0; nt < 8; nt++)
#pragma unroll
            for (int e = 0; e < 4; e++) s[nt][e] = 0.f;
#pragma unroll
        for (int ks = 0; ks < 4; ks++) {
            const uint32_t k0b = (uint32_t)(ks * 16) * 2;
#pragma unroll
            for (int np = 0; np < 4; np++) {
                const uint32_t rbase = (uint32_t)(np * 16 * ASROW) * 2 + k0b;
                uint32_t rh[4], rl[4];
                ldsm4(rh, sK + rbase + boff);
                ldsm4(rl, sKl + rbase + boff);
                mma16816(s[2 * np],     qfh[ks], rh);
                mma16816(s[2 * np],     qfl[ks], rh);
                mma16816(s[2 * np],     qfh[ks], rl);
                mma16816(s[2 * np + 1], qfh[ks], rh + 2);
                mma16816(s[2 * np + 1], qfl[ks], rh + 2);
                mma16816(s[2 * np + 1], qfh[ks], rl + 2);
            }
        }

        const unsigned char* Mt = Msall + kt * 64;
        float mx0 = -1e30f, mx1 = -1e30f;
#pragma unroll
        for (int nt = 0; nt < 8; nt++) {
            const int col = nt * 8 + tig * 2;
            if (Mt[col])     { s[nt][0] = -1e30f; s[nt][2] = -1e30f; }
            if (Mt[col + 1]) { s[nt][1] = -1e30f; s[nt][3] = -1e30f; }
            mx0 = fmaxf(mx0, fmaxf(s[nt][0], s[nt][1]));
            mx1 = fmaxf(mx1, fmaxf(s[nt][2], s[nt][3]));
        }
        mx0 = fmaxf(mx0, __shfl_xor_sync(0xffffffffu, mx0, 1));
        mx0 = fmaxf(mx0, __shfl_xor_sync(0xffffffffu, mx0, 2));
        mx1 = fmaxf(mx1, __shfl_xor_sync(0xffffffffu, mx1, 1));
        mx1 = fmaxf(mx1, __shfl_xor_sync(0xffffffffu, mx1, 2));

        if (mx0 > m0) {
            const float sc0 = __expf(m0 - mx0);
            m0 = mx0;
            l0 *= sc0;
#pragma unroll
            for (int nt = 0; nt < 8; nt++) { out[nt][0] *= sc0; out[nt][1] *= sc0; }
        }
        if (mx1 > m1) {
            const float sc1 = __expf(m1 - mx1);
            m1 = mx1;
            l1 *= sc1;
#pragma unroll
            for (int nt = 0; nt < 8; nt++) { out[nt][2] *= sc1; out[nt][3] *= sc1; }
        }

        float rs0 = 0.f, rs1 = 0.f;
#pragma unroll
        for (int nt = 0; nt < 8; nt++) {
            s[nt][0] = __expf(s[nt][0] - m0);
            s[nt][1] = __expf(s[nt][1] - m0);
            s[nt][2] = __expf(s[nt][2] - m1);
            s[nt][3] = __expf(s[nt][3] - m1);
            rs0 += s[nt][0] + s[nt][1];
            rs1 += s[nt][2] + s[nt][3];
        }
        rs0 += __shfl_xor_sync(0xffffffffu, rs0, 1);
        rs0 += __shfl_xor_sync(0xffffffffu, rs0, 2);
        rs1 += __shfl_xor_sync(0xffffffffu, rs1, 1);
        rs1 += __shfl_xor_sync(0xffffffffu, rs1, 2);
        l0 += rs0;
        l1 += rs1;

#pragma unroll
        for (int kg2 = 0; kg2 < 4; kg2++) {
            uint32_t pa[4];
            pa[0] = packh2(s[2 * kg2][0], s[2 * kg2][1]);
            pa[1] = packh2(s[2 * kg2][2], s[2 * kg2][3]);
            pa[2] = packh2(s[2 * kg2 + 1][0], s[2 * kg2 + 1][1]);
            pa[3] = packh2(s[2 * kg2 + 1][2], s[2 * kg2 + 1][3]);
            const uint32_t kbase = (uint32_t)(kg2 * 16 * ASROW) * 2;
#pragma unroll
            for (int ng = 0; ng < 4; ng++) {
                uint32_t rr[4];
                ldsm4t(rr, sV + kbase + (uint32_t)(ng * 32) + voff);
                mma16816(out[2 * ng],     pa, rr);
                mma16816(out[2 * ng + 1], pa, rr + 2);
            }
        }
        __syncthreads();
    }

    const float i0 = 1.0f / l0, i1 = 1.0f / l1;
    const int r0 = qrow0 + g, r1 = qrow0 + g + 8;
    __half* p0 = ctx + ((size_t)(b * Sq + r0) * Hh + h) * DH;
    __half* p1 = ctx + ((size_t)(b * Sq + r1) * Hh + h) * DH;
#pragma unroll
    for (int nt = 0; nt < 8; nt++) {
        const int dh = nt * 8 + tig * 2;
        *(__half2*)(p0 + dh) = __floats2half2_rn(out[nt][0] * i0, out[nt][1] * i0);
        *(__half2*)(p1 + dh) = __floats2half2_rn(out[nt][2] * i1, out[nt][3] * i1);
    }
}

// ---------------- fused add + LayerNorm (fp32 a + fp16 b; optional fp32/fp16 outs) ----
__global__ __launch_bounds__(256)
void addln_kernel(const float* __restrict__ a, const __half* __restrict__ bhp,
                  const float* __restrict__ g, const float* __restrict__ bt,
                  float* __restrict__ o, __half* __restrict__ oh,
                  float* __restrict__ outf) {
    __shared__ float redS[8], redQ[8], outMV[2];
    const int row = blockIdx.x;
    const int t = threadIdx.x;
    const float* ar = a + (size_t)row * Dm;
    const __half* br = bhp + (size_t)row * Dm;

    float v[4];
    float s = 0.f, sq = 0.f;
#pragma unroll
    for (int i = 0; i < 4; i++) {
        int idx = t + i * 256;
        float x = ar[idx] + __half2float(br[idx]);
        v[i] = x;
        s += x;
        sq = fmaf(x, x, sq);
    }
#pragma unroll
    for (int off = 16; off; off >>= 1) {
        s += __shfl_xor_sync(0xFFFFFFFFu, s, off);
        sq += __shfl_xor_sync(0xFFFFFFFFu, sq, off);
    }
    if ((t & 31) == 0) { redS[t >> 5] = s; redQ[t >> 5] = sq; }
    __syncthreads();
    if (t < 32) {
        float s2 = (t < 8) ? redS[t] : 0.f;
        float q2 = (t < 8) ? redQ[t] : 0.f;
#pragma unroll
        for (int off = 4; off; off >>= 1) {
            s2 += __shfl_xor_sync(0xFFFFFFFFu, s2, off);
            q2 += __shfl_xor_sync(0xFFFFFFFFu, q2, off);
        }
        if (t == 0) {
            float mean = s2 * (1.0f / Dm);
            float var = q2 * (1.0f / Dm) - mean * mean;
            outMV[0] = mean;
            outMV[1] = rsqrtf(var + 1e-5f);
        }
    }
    __syncthreads();
    const float mean = outMV[0], rstd = outMV[1];
#pragma unroll
    for (int i = 0; i < 4; i++) {
        int idx = t + i * 256;
        float y = (v[i] - mean) * rstd * g[idx] + bt[idx];
        if (o)    o[(size_t)row * Dm + idx] = y;
        if (oh)   oh[(size_t)row * Dm + idx] = __float2half_rn(y);
        if (outf) outf[(size_t)row * Dm + idx] = y;
    }
}

// ---------------- launch ----------------
extern "C" void kernel_launch(void* const* d_in, const int* in_sizes, int n_in,
                              void* d_out, int out_size) {
    const float* seq  = (const float*)d_in[0];
    const unsigned char* mask = (const unsigned char*)d_in[1];
    const float* Wqkv = (const float*)d_in[2];
    const float* bqkv = (const float*)d_in[3];
    const float* Wo   = (const float*)d_in[4];
    const float* bo   = (const float*)d_in[5];
    const float* g1   = (const float*)d_in[6];
    const float* b1   = (const float*)d_in[7];
    const float* Wi   = (const float*)d_in[8];
    const float* bi   = (const float*)d_in[9];
    const float* Wout = (const float*)d_in[10];
    const float* bout = (const float*)d_in[11];
    const float* g2   = (const float*)d_in[12];
    const float* b2   = (const float*)d_in[13];
    float* out = (float*)d_out;

    __half *seqh, *seql, *Bqkh, *Bqkl, *Bvh, *Woh, *Wih, *Wouth;
    __half *qh, *ql, *kh, *kl, *vh, *ctxh, *xh, *hh, *attnh, *yh;
    float *x;
    cudaGetSymbolAddress((void**)&seqh, g_seqh);   cudaGetSymbolAddress((void**)&seql, g_seql);
    cudaGetSymbolAddress((void**)&Bqkh, g_Bqkh);   cudaGetSymbolAddress((void**)&Bqkl, g_Bqkl);
    cudaGetSymbolAddress((void**)&Bvh, g_Bvh);
    cudaGetSymbolAddress((void**)&Woh, g_Woh);
    cudaGetSymbolAddress((void**)&Wih, g_Wih);
    cudaGetSymbolAddress((void**)&Wouth, g_Wouth);
    cudaGetSymbolAddress((void**)&qh, g_qh);       cudaGetSymbolAddress((void**)&ql, g_ql);
    cudaGetSymbolAddress((void**)&kh, g_kh);       cudaGetSymbolAddress((void**)&kl, g_kl);
    cudaGetSymbolAddress((void**)&vh, g_vh);       cudaGetSymbolAddress((void**)&ctxh, g_ctxh);
    cudaGetSymbolAddress((void**)&xh, g_xh);       cudaGetSymbolAddress((void**)&hh, g_hh);
    cudaGetSymbolAddress((void**)&attnh, g_attnh); cudaGetSymbolAddress((void**)&x, g_x);
    cudaGetSymbolAddress((void**)&yh, g_yh);

    const int SM3 = 2 * 4 * TILE_B;   // 147456
    const int SM1 = 2 * 2 * TILE_B;   // 73728
    cudaFuncSetAttribute(mma_gemm<3, 3, 1>, cudaFuncAttributeMaxDynamicSharedMemorySize, SM3);
    cudaFuncSetAttribute(mma_gemm<4, 1, 2>, cudaFuncAttributeMaxDynamicSharedMemorySize, SM1);
    cudaFuncSetAttribute(mma_gemm<5, 1, 2>, cudaFuncAttributeMaxDynamicSharedMemorySize, SM1);
    cudaFuncSetAttribute(mma_gemm<2, 1, 2>, cudaFuncAttributeMaxDynamicSharedMemorySize, SM1);
    cudaFuncSetAttribute(attn_mma, cudaFuncAttributeMaxDynamicSharedMemorySize, ATT_SMEM);

    // fused prologue: all weight packs + seq split in one launch
    prologue_kernel<<<PRO_BLOCKS, 256>>>(Wqkv, Wo, Wi, Wout, seq,
                                         Bqkh, Bqkl, Bvh, Woh, Wih, Wouth, seqh, seql);

    // QK projection (3-term) -> q(hi/lo)*8, k(hi/lo)
    mma_gemm<3, 3, 1><<<dim3(2048 / 128, ROWS / 128), 256, SM3>>>(
        seqh, seql, Bqkh, Bqkl, bqkv, qh, ql, kh, kl, nullptr, nullptr, Dm, 2048);

    // V projection (1-term) -> v fp16
    mma_gemm<4, 1, 2><<<dim3(1024 / 128, ROWS / 128), 256, SM1>>>(
        seqh, nullptr, Bvh, nullptr, bqkv,
        nullptr, nullptr, nullptr, nullptr, vh, nullptr, Dm, 1024);

    // tensor-core flash attention -> ctx fp16
    attn_mma<<<dim3(8, Hh, Bz), 256, ATT_SMEM>>>(qh, ql, kh, kl, vh, mask, ctxh);

    // output projection (1-term) -> attn fp16
    mma_gemm<5, 1, 2><<<dim3(Dm / 128, ROWS / 128), 256, SM1>>>(
        ctxh, nullptr, Woh, nullptr, bo,
        nullptr, nullptr, nullptr, nullptr, nullptr, attnh, Dm, Dm);

    // x = LN(seq + attn) -> x fp32 + xh fp16
    addln_kernel<<<ROWS, 256>>>(seq, attnh, g1, b1, x, xh, nullptr);

    // h = gelu(x @ Wi + bi) (1-term, fast erf) -> fp16
    mma_gemm<2, 1, 2><<<dim3(Ii / 128, ROWS / 128), 256, SM1>>>(
        xh, nullptr, Wih, nullptr, bi,
        nullptr, nullptr, nullptr, nullptr, nullptr, hh, Dm, Ii);

    // y = h @ Wout + bout (1-term) -> fp16
    mma_gemm<5, 1, 2><<<dim3(Dm / 128, ROWS / 128), 256, SM1>>>(
        hh, nullptr, Wouth, nullptr, bout,
        nullptr, nullptr, nullptr, nullptr, nullptr, yh, Ii, Dm);

    // out = LN(x + y)
    addln_kernel<<<ROWS, 256>>>(x, yh, g2, b2, nullptr, nullptr, out);
}